// round 1
// baseline (speedup 1.0000x reference)
#include <cuda_runtime.h>
#include <math.h>

#define BB   8
#define CC   64
#define OUTC 32
#define HW   64
#define NPIX 4096   // 64*64

// ---------------- scratch (static device globals; no allocation) ----------------
__device__ float g_mean[BB * CC];
__device__ float g_energy[BB * CC];
__device__ float g_scale[BB * CC];
__device__ float g_xrfa[BB * CC * NPIX];   // 8 MB

__device__ __forceinline__ float sigm_(float v) { return 1.f / (1.f + __expf(-v)); }
__device__ __forceinline__ float silu_(float v) { return v / (1.f + __expf(-v)); }

// ==================================================================================
// Kernel 1: per-(b,c) 64x64 DFT magnitude mean + spatial mean.
// Hermitian symmetry: only k2 in [0,32] computed; interior columns counted twice.
// ==================================================================================
__global__ __launch_bounds__(256) void fft_energy_kernel(const float* __restrict__ x)
{
    __shared__ float xs[64 * 64];
    __shared__ float Ar[64 * 33];
    __shared__ float Ai[64 * 33];
    __shared__ float ct[64], st[64];
    __shared__ float red[256];

    const int tid = threadIdx.x;
    const int bc  = blockIdx.x;

    if (tid < 64) {
        float ang = 0.09817477042468103f * (float)tid;   // 2*pi/64 * tid
        ct[tid] = cosf(ang);
        st[tid] = sinf(ang);
    }

    const float* xp = x + (size_t)bc * NPIX;
    float lsum = 0.f;
    for (int i = tid; i < 4096; i += 256) {
        float v = xp[i];
        xs[i] = v;
        lsum += v;
    }
    red[tid] = lsum;
    __syncthreads();
    for (int s = 128; s > 0; s >>= 1) {
        if (tid < s) red[tid] += red[tid + s];
        __syncthreads();
    }
    if (tid == 0) g_mean[bc] = red[0] * (1.f / 4096.f);

    // ---- pass 1: A[n1][k2] = sum_n2 x[n1][n2] * e^{-2pi i k2 n2 / 64},  k2 in [0,32]
    for (int idx = tid; idx < 64 * 33; idx += 256) {
        int n1 = idx / 33;
        int k2 = idx - n1 * 33;
        const float* row = &xs[n1 * 64];
        float ar = 0.f, ai = 0.f;
#pragma unroll 16
        for (int n2 = 0; n2 < 64; n2++) {
            int   mm = (k2 * n2) & 63;
            float v  = row[n2];
            ar += v * ct[mm];
            ai -= v * st[mm];
        }
        Ar[idx] = ar;
        Ai[idx] = ai;
    }
    __syncthreads();

    // ---- pass 2: X[k1][k2] = sum_n1 A[n1][k2] * e^{-2pi i k1 n1 / 64}
    float esum = 0.f;
    for (int idx = tid; idx < 64 * 33; idx += 256) {
        int k1 = idx / 33;
        int k2 = idx - k1 * 33;
        float re = 0.f, im = 0.f;
#pragma unroll 16
        for (int n1 = 0; n1 < 64; n1++) {
            int   mm = (k1 * n1) & 63;
            float cv = ct[mm], sv = st[mm];
            float ar = Ar[n1 * 33 + k2];
            float ai = Ai[n1 * 33 + k2];
            re += ar * cv + ai * sv;
            im += ai * cv - ar * sv;
        }
        float mag = sqrtf(re * re + im * im);
        esum += (k2 == 0 || k2 == 32) ? mag : 2.f * mag;
    }
    red[tid] = esum;
    __syncthreads();
    for (int s = 128; s > 0; s >>= 1) {
        if (tid < s) red[tid] += red[tid + s];
        __syncthreads();
    }
    if (tid == 0) g_energy[bc] = red[0] * (1.f / 4096.f);
}

// ==================================================================================
// Kernel 2: FGCA gate pipeline -> per-(b,c) channel scale.
// One block per batch, 64 threads (one per channel).
// ==================================================================================
__global__ __launch_bounds__(64) void gates_kernel(
    const float* __restrict__ ex_w, const float* __restrict__ ey_w, const float* __restrict__ ez_w,
    const float* __restrict__ ff_w, const float* __restrict__ ff_b,
    const float* __restrict__ g1_w, const float* __restrict__ g1_b,
    const float* __restrict__ g2_w, const float* __restrict__ g2_b)
{
    const int b = blockIdx.x;
    const int c = threadIdx.x;

    __shared__ float se[64], smn[64], smy[64], smz[64];
    __shared__ float ax[64], ay[64], az[64], af[64], hv[16];

    se[c]  = g_energy[b * 64 + c];
    smn[c] = g_mean[b * 64 + c];
    __syncthreads();

    // rank via stable argsort(argsort(-energy)) semantics
    float e    = se[c];
    int   rank = 0;
#pragma unroll 16
    for (int c2 = 0; c2 < 64; c2++) {
        float e2 = se[c2];
        rank += (e2 > e) || (e2 == e && c2 < c);
    }
    float mask = (rank < 32) ? 1.f : 0.f;
    smy[c] = smn[c] * mask;
    smz[c] = smn[c] * (1.f - mask);
    __syncthreads();

    // ECA: 1D conv (k=3, pad=1) over channel axis, then sigmoid
    {
        float w0 = ex_w[0], w1 = ex_w[1], w2 = ex_w[2];
        float v = smn[c] * w1;
        if (c > 0)  v += smn[c - 1] * w0;
        if (c < 63) v += smn[c + 1] * w2;
        ax[c] = sigm_(v);
    }
    {
        float w0 = ey_w[0], w1 = ey_w[1], w2 = ey_w[2];
        float v = smy[c] * w1;
        if (c > 0)  v += smy[c - 1] * w0;
        if (c < 63) v += smy[c + 1] * w2;
        ay[c] = sigm_(v);
    }
    {
        float w0 = ez_w[0], w1 = ez_w[1], w2 = ez_w[2];
        float v = smz[c] * w1;
        if (c > 0)  v += smz[c - 1] * w0;
        if (c < 63) v += smz[c + 1] * w2;
        az[c] = sigm_(v);
    }
    __syncthreads();

    // a_f: grouped 1x1 conv (groups=4) on concat([a_y, a_z])
    {
        int g = c >> 4;
        const float* src  = (g < 2) ? ay : az;
        int base          = (g < 2) ? g * 32 : (g - 2) * 32;
        float s = ff_b[c];
#pragma unroll 8
        for (int j = 0; j < 32; j++) s += ff_w[c * 32 + j] * src[base + j];
        af[c] = s;
    }
    __syncthreads();

    // gate MLP: hidden(16) = silu(g1 @ [a_f, a_x]);  g = sigmoid(g2 @ hidden)
    if (c < 16) {
        float hsum = g1_b[c];
#pragma unroll 8
        for (int i = 0; i < 64; i++) hsum += g1_w[c * 128 + i] * af[i];
#pragma unroll 8
        for (int i = 0; i < 64; i++) hsum += g1_w[c * 128 + 64 + i] * ax[i];
        hv[c] = silu_(hsum);
    }
    __syncthreads();

    float gs = g2_b[c];
#pragma unroll
    for (int j = 0; j < 16; j++) gs += g2_w[c * 16 + j] * hv[j];
    float gg = sigm_(gs);

    g_scale[b * 64 + c] = gg * af[c] + (1.f - gg) * ax[c];
}

// ==================================================================================
// Kernel 3: ReceptiveFieldAttentionConv, fully fused per pixel.
// 128 threads/block, 2 adjacent pixels per thread, 256 px/block, grid = 8*16.
// ==================================================================================
__global__ __launch_bounds__(128) void rfa_kernel(
    const float* __restrict__ x,
    const float* __restrict__ sc_w, const float* __restrict__ sc_b,
    const float* __restrict__ ac_w, const float* __restrict__ ac_b,
    const float* __restrict__ oc_w, const float* __restrict__ oc_b,
    const float* __restrict__ bng, const float* __restrict__ bnb,
    const float* __restrict__ bnm, const float* __restrict__ bnv)
{
    __shared__ float s_scw[5184];
    __shared__ float s_scb[576];
    __shared__ float s_acw[576];
    __shared__ float s_acb[576];
    __shared__ float s_ocw[9216];
    __shared__ float s_ob[64];
    __shared__ float s_bs[64], s_bb[64];

    const int tid = threadIdx.x;
    for (int i = tid; i < 5184; i += 128) s_scw[i] = sc_w[i];
    for (int i = tid; i < 576; i += 128) {
        s_scb[i] = sc_b[i];
        s_acw[i] = ac_w[i];
        s_acb[i] = ac_b[i];
    }
    for (int i = tid; i < 9216; i += 128) s_ocw[i] = oc_w[i];
    if (tid < 64) {
        float s   = bng[tid] * rsqrtf(bnv[tid] + 1e-5f);
        s_bs[tid] = s;
        s_bb[tid] = bnb[tid] - bnm[tid] * s;
        s_ob[tid] = oc_b[tid];
    }
    __syncthreads();

    const int b     = blockIdx.x >> 4;
    const int chunk = blockIdx.x & 15;
    const int pix   = chunk * 256 + tid * 2;    // within-batch linear pixel, even
    const int h     = pix >> 6;
    const int w0    = pix & 63;

    const float* xb = x + (size_t)b * CC * NPIX;
    const bool has_l = (w0 > 0);
    const bool has_r = (w0 + 2 < 64);

    for (int og = 0; og < 4; og++) {
        float acc0[16], acc1[16];
#pragma unroll
        for (int oo = 0; oo < 16; oo++) {
            acc0[oo] = s_ob[og * 16 + oo];
            acc1[oo] = s_ob[og * 16 + oo];
        }

        for (int cl = 0; cl < 16; cl++) {
            const int c = og * 16 + cl;
            const float* xc = xb + (size_t)c * NPIX;

            // neighborhood: rows h-1..h+1, cols w0-1..w0+2, zero padded
            float n[3][4];
#pragma unroll
            for (int r = 0; r < 3; r++) {
                int   hh = h + r - 1;
                float v0 = 0.f, v1 = 0.f, v2 = 0.f, v3 = 0.f;
                if (hh >= 0 && hh < 64) {
                    const float* rowp = xc + hh * 64;
                    float2 mid = *(const float2*)(rowp + w0);
                    v1 = mid.x; v2 = mid.y;
                    if (has_l) v0 = rowp[w0 - 1];
                    if (has_r) v3 = rowp[w0 + 2];
                }
                n[r][0] = v0; n[r][1] = v1; n[r][2] = v2; n[r][3] = v3;
            }

            // avgpool3 values (count_include_pad -> always /9)
            float p0 = 0.f, p1 = 0.f;
#pragma unroll
            for (int r = 0; r < 3; r++) {
                p0 += n[r][0] + n[r][1] + n[r][2];
                p1 += n[r][1] + n[r][2] + n[r][3];
            }
            p0 *= (1.f / 9.f);
            p1 *= (1.f / 9.f);

            // arf softmax over 9 RF positions
            float a0[9], a1[9];
            float m0 = -1e30f, m1 = -1e30f;
#pragma unroll
            for (int j = 0; j < 9; j++) {
                float aw = s_acw[c * 9 + j];
                float ab = s_acb[c * 9 + j];
                a0[j] = p0 * aw + ab;
                a1[j] = p1 * aw + ab;
                m0 = fmaxf(m0, a0[j]);
                m1 = fmaxf(m1, a1[j]);
            }
            float sum0 = 0.f, sum1 = 0.f;
#pragma unroll
            for (int j = 0; j < 9; j++) {
                a0[j] = __expf(a0[j] - m0);
                a1[j] = __expf(a1[j] - m1);
                sum0 += a0[j];
                sum1 += a1[j];
            }
            float r0 = 1.f / sum0;
            float r1 = 1.f / sum1;

            // depthwise conv (9 kernels) + silu + softmax weight
            float t0[9], t1[9];
#pragma unroll
            for (int j = 0; j < 9; j++) {
                const float* wj = &s_scw[(c * 9 + j) * 9];
                float d0 = 0.f, d1 = 0.f;
#pragma unroll
                for (int ty = 0; ty < 3; ty++) {
#pragma unroll
                    for (int tx = 0; tx < 3; tx++) {
                        float wv = wj[ty * 3 + tx];
                        d0 += n[ty][tx] * wv;
                        d1 += n[ty][tx + 1] * wv;
                    }
                }
                float bias = s_scb[c * 9 + j];
                d0 += bias;
                d1 += bias;
                t0[j] = silu_(d0) * a0[j] * r0;
                t1[j] = silu_(d1) * a1[j] * r1;
            }

            // grouped projection: 16 outputs, 9 taps each (each weight feeds 2 px)
#pragma unroll
            for (int oo = 0; oo < 16; oo++) {
                const float* owo = &s_ocw[(((og * 16 + oo) * 16) + cl) * 9];
                float ac0 = acc0[oo], ac1 = acc1[oo];
#pragma unroll
                for (int j = 0; j < 9; j++) {
                    float wv = owo[j];
                    ac0 += t0[j] * wv;
                    ac1 += t1[j] * wv;
                }
                acc0[oo] = ac0;
                acc1[oo] = ac1;
            }
        }

        // BN + SiLU + store
#pragma unroll
        for (int oo = 0; oo < 16; oo++) {
            int   o  = og * 16 + oo;
            float y0 = acc0[oo] * s_bs[o] + s_bb[o];
            float y1 = acc1[oo] * s_bs[o] + s_bb[o];
            float2 outv = make_float2(silu_(y0), silu_(y1));
            *(float2*)&g_xrfa[((size_t)(b * 64 + o)) * NPIX + pix] = outv;
        }
    }
}

// ==================================================================================
// Kernel 4: fuse = silu(bn(1x1 conv over concat(x_rfa, x * scale))).
// 128 threads/block, 2 px per thread (float2), grid = 8*16.
// ==================================================================================
__global__ __launch_bounds__(128) void fuse_kernel(
    const float* __restrict__ x,
    const float* __restrict__ fu_w, const float* __restrict__ fu_b,
    const float* __restrict__ bng, const float* __restrict__ bnb,
    const float* __restrict__ bnm, const float* __restrict__ bnv,
    float* __restrict__ out)
{
    __shared__ float ws[4096];
    __shared__ float ss32[32];
    __shared__ float bf[32];
    __shared__ float sscale[64];

    const int tid = threadIdx.x;
    const int b     = blockIdx.x >> 4;
    const int chunk = blockIdx.x & 15;

    if (tid < 32) {
        float s = bng[tid] * rsqrtf(bnv[tid] + 1e-5f);
        ss32[tid] = s;
        bf[tid]   = fu_b[tid] * s + bnb[tid] - bnm[tid] * s;
    }
    if (tid >= 64 && tid < 128) sscale[tid - 64] = g_scale[b * 64 + (tid - 64)];
    __syncthreads();
    for (int i = tid; i < 4096; i += 128) ws[i] = fu_w[i] * ss32[i >> 7];
    __syncthreads();

    const int pix = chunk * 256 + tid * 2;
    const float* xb = x + (size_t)b * CC * NPIX;
    const float* rb = g_xrfa + (size_t)b * CC * NPIX;

    float2 acc[32];
#pragma unroll
    for (int o = 0; o < 32; o++) acc[o] = make_float2(bf[o], bf[o]);

    for (int c = 0; c < 64; c++) {
        float2 xa = *(const float2*)(rb + (size_t)c * NPIX + pix);
        float2 xr = *(const float2*)(xb + (size_t)c * NPIX + pix);
        float  sc = sscale[c];
        xr.x *= sc;
        xr.y *= sc;
#pragma unroll
        for (int o = 0; o < 32; o++) {
            float wA = ws[o * 128 + c];
            float wB = ws[o * 128 + 64 + c];
            acc[o].x += wA * xa.x + wB * xr.x;
            acc[o].y += wA * xa.y + wB * xr.y;
        }
    }

#pragma unroll
    for (int o = 0; o < 32; o++) {
        float2 r = make_float2(silu_(acc[o].x), silu_(acc[o].y));
        *(float2*)&out[((size_t)(b * 32 + o)) * NPIX + pix] = r;
    }
}

// ==================================================================================
extern "C" void kernel_launch(void* const* d_in, const int* in_sizes, int n_in,
                              void* d_out, int out_size)
{
    const float* x      = (const float*)d_in[0];
    const float* sc_w   = (const float*)d_in[1];
    const float* sc_b   = (const float*)d_in[2];
    const float* ac_w   = (const float*)d_in[3];
    const float* ac_b   = (const float*)d_in[4];
    const float* oc_w   = (const float*)d_in[5];
    const float* oc_b   = (const float*)d_in[6];
    const float* oc_bng = (const float*)d_in[7];
    const float* oc_bnb = (const float*)d_in[8];
    const float* oc_bnm = (const float*)d_in[9];
    const float* oc_bnv = (const float*)d_in[10];
    const float* ex_w   = (const float*)d_in[11];
    const float* ey_w   = (const float*)d_in[12];
    const float* ez_w   = (const float*)d_in[13];
    const float* ff_w   = (const float*)d_in[14];
    const float* ff_b   = (const float*)d_in[15];
    const float* g1_w   = (const float*)d_in[16];
    const float* g1_b   = (const float*)d_in[17];
    const float* g2_w   = (const float*)d_in[18];
    const float* g2_b   = (const float*)d_in[19];
    const float* fu_w   = (const float*)d_in[20];
    const float* fu_b   = (const float*)d_in[21];
    const float* fu_bng = (const float*)d_in[22];
    const float* fu_bnb = (const float*)d_in[23];
    const float* fu_bnm = (const float*)d_in[24];
    const float* fu_bnv = (const float*)d_in[25];

    fft_energy_kernel<<<BB * CC, 256>>>(x);
    gates_kernel<<<BB, 64>>>(ex_w, ey_w, ez_w, ff_w, ff_b, g1_w, g1_b, g2_w, g2_b);
    rfa_kernel<<<BB * 16, 128>>>(x, sc_w, sc_b, ac_w, ac_b, oc_w, oc_b,
                                 oc_bng, oc_bnb, oc_bnm, oc_bnv);
    fuse_kernel<<<BB * 16, 128>>>(x, fu_w, fu_b, fu_bng, fu_bnb, fu_bnm, fu_bnv,
                                  (float*)d_out);
}

// round 4
// speedup vs baseline: 1.4979x; 1.4979x over previous
#include <cuda_runtime.h>
#include <math.h>

#define BB   8
#define CC   64
#define OUTC 32
#define NPIX 4096   // 64*64

// ---------------- scratch (static device globals; no allocation) ----------------
__device__ float g_mean[BB * CC];
__device__ float g_energy[BB * CC];
__device__ float g_scale[BB * CC];

__device__ __forceinline__ float sigm_(float v) { return 1.f / (1.f + __expf(-v)); }
__device__ __forceinline__ float silu_(float v) { return v / (1.f + __expf(-v)); }

#define LD4(p) (*(const float4*)(p))

// fma of scalar s times float4 vec into float4 acc (params renamed: no x/y/z/w collision)
#define FMA4(Dst, Vec, Scl) { (Dst).x = fmaf((Vec).x, (Scl), (Dst).x); \
                              (Dst).y = fmaf((Vec).y, (Scl), (Dst).y); \
                              (Dst).z = fmaf((Vec).z, (Scl), (Dst).z); \
                              (Dst).w = fmaf((Vec).w, (Scl), (Dst).w); }

// ==================================================================================
// Kernel 1: per-(b,c) 64x64 DFT magnitude mean + spatial mean.
// Pass1: twiddles via register rotation recurrence (no smem conflicts).
// Pass2: 4 k1-rows per thread; twiddles from one broadcast lookup + 90-deg rotations.
// ==================================================================================
__device__ __forceinline__ void rot90_(float c, float s, int m, float& cv, float& sv)
{
    // angle offset m * pi/2:  m0:(c,s)  m1:(-s,c)  m2:(-c,-s)  m3:(s,-c)
    float cs = (m & 1) ? s : c;
    float sn = (m & 1) ? c : s;
    cv = (m == 1 || m == 2) ? -cs : cs;
    sv = (m >= 2) ? -sn : sn;
}

__global__ __launch_bounds__(256) void fft_energy_kernel(const float* __restrict__ x)
{
    __shared__ float xs[4096];
    __shared__ float Ar[2112];   // [n1][k2<=32], stride 33
    __shared__ float Ai[2112];
    __shared__ float ct[64], st[64];
    __shared__ float red[256];

    const int tid = threadIdx.x;
    const int bc  = blockIdx.x;

    if (tid < 64) {
        float sv, cv;
        sincosf(0.09817477042468103f * (float)tid, &sv, &cv);   // 2*pi/64 * tid
        ct[tid] = cv;
        st[tid] = sv;
    }

    const float* xp = x + (size_t)bc * NPIX;
    float lsum = 0.f;
    for (int i = tid; i < 4096; i += 256) {
        float v = xp[i];
        xs[i] = v;
        lsum += v;
    }
    red[tid] = lsum;
    __syncthreads();
    for (int s = 128; s > 0; s >>= 1) {
        if (tid < s) red[tid] += red[tid + s];
        __syncthreads();
    }
    if (tid == 0) g_mean[bc] = red[0] * (1.f / 4096.f);

    // ---- pass 1: A[n1][k2] = sum_n2 x[n1][n2] * e^{-i 2pi k2 n2/64}, k2 in [0,32]
    // tasks: (n1a in 0..15) x (k2 in 0..32); each computes rows n1a+16r, r=0..3
    for (int t = tid; t < 528; t += 256) {
        int n1a = t / 33;
        int k2  = t - n1a * 33;
        float sd, cd;
        __sincosf(0.09817477042468103f * (float)k2, &sd, &cd);
        float cv = 1.f, sv = 0.f;
        float a0r = 0.f, a0i = 0.f, a1r = 0.f, a1i = 0.f;
        float a2r = 0.f, a2i = 0.f, a3r = 0.f, a3i = 0.f;
        const float* x0 = &xs[n1a * 64];
#pragma unroll 8
        for (int n2 = 0; n2 < 64; n2++) {
            float v0 = x0[n2];
            float v1 = x0[n2 + 1024];
            float v2 = x0[n2 + 2048];
            float v3 = x0[n2 + 3072];
            a0r += v0 * cv;  a0i -= v0 * sv;
            a1r += v1 * cv;  a1i -= v1 * sv;
            a2r += v2 * cv;  a2i -= v2 * sv;
            a3r += v3 * cv;  a3i -= v3 * sv;
            float ncv = cv * cd - sv * sd;
            float nsv = sv * cd + cv * sd;
            cv = ncv; sv = nsv;
        }
        Ar[n1a * 33 + k2]          = a0r;  Ai[n1a * 33 + k2]          = a0i;
        Ar[(n1a + 16) * 33 + k2]   = a1r;  Ai[(n1a + 16) * 33 + k2]   = a1i;
        Ar[(n1a + 32) * 33 + k2]   = a2r;  Ai[(n1a + 32) * 33 + k2]   = a2i;
        Ar[(n1a + 48) * 33 + k2]   = a3r;  Ai[(n1a + 48) * 33 + k2]   = a3i;
    }
    __syncthreads();

    // ---- pass 2: X[k1][k2] = sum_n1 A[n1][k2] * e^{-i 2pi k1 n1/64}
    // tasks: (k1a in 0..15) x (k2 in 0..32); rows k1a+16r differ by (pi/2)*r*n1
    float esum = 0.f;
    for (int t = tid; t < 528; t += 256) {
        int k1a = t / 33;
        int k2  = t - k1a * 33;
        float r0r = 0.f, r0i = 0.f, r1r = 0.f, r1i = 0.f;
        float r2r = 0.f, r2i = 0.f, r3r = 0.f, r3i = 0.f;
        int mm = 0;
#pragma unroll 8
        for (int n1 = 0; n1 < 64; n1++) {
            float ar = Ar[n1 * 33 + k2];
            float ai = Ai[n1 * 33 + k2];
            float c0 = ct[mm], s0 = st[mm];
            mm = (mm + k1a) & 63;
            r0r += ar * c0 + ai * s0;
            r0i += ai * c0 - ar * s0;
            int m1 = n1 & 3;
            int m2 = (n1 << 1) & 3;
            int m3 = (m1 + m2) & 3;
            float cv, sv;
            rot90_(c0, s0, m1, cv, sv);
            r1r += ar * cv + ai * sv;  r1i += ai * cv - ar * sv;
            rot90_(c0, s0, m2, cv, sv);
            r2r += ar * cv + ai * sv;  r2i += ai * cv - ar * sv;
            rot90_(c0, s0, m3, cv, sv);
            r3r += ar * cv + ai * sv;  r3i += ai * cv - ar * sv;
        }
        float wgt = (k2 == 0 || k2 == 32) ? 1.f : 2.f;
        esum += wgt * (sqrtf(r0r * r0r + r0i * r0i) + sqrtf(r1r * r1r + r1i * r1i) +
                       sqrtf(r2r * r2r + r2i * r2i) + sqrtf(r3r * r3r + r3i * r3i));
    }
    __syncthreads();
    red[tid] = esum;
    __syncthreads();
    for (int s = 128; s > 0; s >>= 1) {
        if (tid < s) red[tid] += red[tid + s];
        __syncthreads();
    }
    if (tid == 0) g_energy[bc] = red[0] * (1.f / 4096.f);
}

// ==================================================================================
// Kernel 2: FGCA gate pipeline -> per-(b,c) channel scale. One block per batch.
// ==================================================================================
__global__ __launch_bounds__(64) void gates_kernel(
    const float* __restrict__ ex_w, const float* __restrict__ ey_w, const float* __restrict__ ez_w,
    const float* __restrict__ ff_w, const float* __restrict__ ff_b,
    const float* __restrict__ g1_w, const float* __restrict__ g1_b,
    const float* __restrict__ g2_w, const float* __restrict__ g2_b)
{
    const int b = blockIdx.x;
    const int c = threadIdx.x;

    __shared__ float se[64], smn[64], smy[64], smz[64];
    __shared__ float ax[64], ay[64], az[64], af[64], hv[16];

    se[c]  = g_energy[b * 64 + c];
    smn[c] = g_mean[b * 64 + c];
    __syncthreads();

    float e    = se[c];
    int   rank = 0;
#pragma unroll 16
    for (int c2 = 0; c2 < 64; c2++) {
        float e2 = se[c2];
        rank += (e2 > e) || (e2 == e && c2 < c);
    }
    float mask = (rank < 32) ? 1.f : 0.f;
    smy[c] = smn[c] * mask;
    smz[c] = smn[c] * (1.f - mask);
    __syncthreads();

    {
        float w0 = ex_w[0], w1 = ex_w[1], w2 = ex_w[2];
        float v = smn[c] * w1;
        if (c > 0)  v += smn[c - 1] * w0;
        if (c < 63) v += smn[c + 1] * w2;
        ax[c] = sigm_(v);
    }
    {
        float w0 = ey_w[0], w1 = ey_w[1], w2 = ey_w[2];
        float v = smy[c] * w1;
        if (c > 0)  v += smy[c - 1] * w0;
        if (c < 63) v += smy[c + 1] * w2;
        ay[c] = sigm_(v);
    }
    {
        float w0 = ez_w[0], w1 = ez_w[1], w2 = ez_w[2];
        float v = smz[c] * w1;
        if (c > 0)  v += smz[c - 1] * w0;
        if (c < 63) v += smz[c + 1] * w2;
        az[c] = sigm_(v);
    }
    __syncthreads();

    {
        int g = c >> 4;
        const float* src = (g < 2) ? ay : az;
        int base         = (g < 2) ? g * 32 : (g - 2) * 32;
        float s = ff_b[c];
#pragma unroll 8
        for (int j = 0; j < 32; j++) s += ff_w[c * 32 + j] * src[base + j];
        af[c] = s;
    }
    __syncthreads();

    if (c < 16) {
        float hsum = g1_b[c];
#pragma unroll 8
        for (int i = 0; i < 64; i++) hsum += g1_w[c * 128 + i] * af[i];
#pragma unroll 8
        for (int i = 0; i < 64; i++) hsum += g1_w[c * 128 + 64 + i] * ax[i];
        hv[c] = silu_(hsum);
    }
    __syncthreads();

    float gs = g2_b[c];
#pragma unroll
    for (int j = 0; j < 16; j++) gs += g2_w[c * 16 + j] * hv[j];
    float gg = sigm_(gs);

    g_scale[b * 64 + c] = gg * af[c] + (1.f - gg) * ax[c];
}

// ==================================================================================
// Kernel 3: RFA conv + FGCA apply + final 1x1 fuse + BN + SiLU, fully fused.
// 64 threads/block, 2 px/thread, grid = B*32. Weights padded 9->12 for float4 LDS.
// ==================================================================================
__global__ __launch_bounds__(64) void rfa_fuse_kernel(
    const float* __restrict__ x,
    const float* __restrict__ sc_w, const float* __restrict__ sc_b,
    const float* __restrict__ ac_w, const float* __restrict__ ac_b,
    const float* __restrict__ oc_w, const float* __restrict__ oc_b,
    const float* __restrict__ bng, const float* __restrict__ bnb,
    const float* __restrict__ bnm, const float* __restrict__ bnv,
    const float* __restrict__ fu_w, const float* __restrict__ fu_b,
    const float* __restrict__ fbng, const float* __restrict__ fbnb,
    const float* __restrict__ fbnm, const float* __restrict__ fbnv,
    float* __restrict__ out)
{
    __shared__ __align__(16) float s_scw[6912];    // (c*9+j) stride 12
    __shared__ __align__(16) float s_scb[768];     // c stride 12
    __shared__ __align__(16) float s_acw[768];
    __shared__ __align__(16) float s_acb[768];
    __shared__ __align__(16) float s_ocw[12288];   // (o*16+cl) stride 12
    __shared__ __align__(16) float s_wsT[4096];    // [c][o]: fu_w[o][c]*bnS[o]
    __shared__ __align__(16) float s_bf[32];
    __shared__ float s_ob[64], s_bs[64], s_bb[64], s_scale[64], s_s32[32];

    const int tid   = threadIdx.x;
    const int b     = blockIdx.x >> 5;
    const int chunk = blockIdx.x & 31;

    for (int i = tid; i < 5184; i += 64) { int g = i / 9, j = i - g * 9; s_scw[g * 12 + j] = sc_w[i]; }
    for (int i = tid; i < 576; i += 64) {
        int cc = i / 9, j = i - cc * 9;
        s_scb[cc * 12 + j] = sc_b[i];
        s_acw[cc * 12 + j] = ac_w[i];
        s_acb[cc * 12 + j] = ac_b[i];
    }
    for (int i = tid; i < 9216; i += 64) { int g = i / 9, j = i - g * 9; s_ocw[g * 12 + j] = oc_w[i]; }
    if (tid < 64) {
        float s = bng[tid] * rsqrtf(bnv[tid] + 1e-5f);
        s_bs[tid]    = s;
        s_bb[tid]    = bnb[tid] - bnm[tid] * s;
        s_ob[tid]    = oc_b[tid];
        s_scale[tid] = g_scale[b * 64 + tid];
    }
    if (tid < 32) {
        float s = fbng[tid] * rsqrtf(fbnv[tid] + 1e-5f);
        s_s32[tid] = s;
        s_bf[tid]  = fu_b[tid] * s + fbnb[tid] - fbnm[tid] * s;
    }
    __syncthreads();
    for (int i = tid; i < 4096; i += 64) {
        int o = i & 31, cc = i >> 5;
        s_wsT[i] = fu_w[o * 128 + cc] * s_s32[o];
    }
    __syncthreads();

    const int pix = chunk * 128 + tid * 2;
    const int h   = pix >> 6;
    const int w0  = pix & 63;
    const float* xb = x + (size_t)b * CC * NPIX;
    const bool has_l = (w0 > 0);
    const bool has_r = (w0 < 62);

    // fused 1x1-conv accumulators: 32 outputs x 2 px
    float4 f0[8], f1[8];
#pragma unroll
    for (int q = 0; q < 8; q++) { f0[q] = LD4(&s_bf[q * 4]); f1[q] = f0[q]; }

    for (int og = 0; og < 4; og++) {
        float acc0[16], acc1[16];
#pragma unroll
        for (int oo = 0; oo < 16; oo++) {
            acc0[oo] = s_ob[og * 16 + oo];
            acc1[oo] = acc0[oo];
        }

        for (int cl = 0; cl < 16; cl++) {
            const int c = og * 16 + cl;
            const float* xc = xb + (size_t)c * NPIX;

            float n[3][4];
#pragma unroll
            for (int r = 0; r < 3; r++) {
                int   hh = h + r - 1;
                float v0 = 0.f, v1 = 0.f, v2 = 0.f, v3 = 0.f;
                if (hh >= 0 && hh < 64) {
                    const float* rowp = xc + hh * 64;
                    float2 mid = *(const float2*)(rowp + w0);
                    v1 = mid.x; v2 = mid.y;
                    if (has_l) v0 = rowp[w0 - 1];
                    if (has_r) v3 = rowp[w0 + 2];
                }
                n[r][0] = v0; n[r][1] = v1; n[r][2] = v2; n[r][3] = v3;
            }

            float p0 = 0.f, p1 = 0.f;
#pragma unroll
            for (int r = 0; r < 3; r++) {
                p0 += n[r][0] + n[r][1] + n[r][2];
                p1 += n[r][1] + n[r][2] + n[r][3];
            }
            p0 *= (1.f / 9.f);
            p1 *= (1.f / 9.f);

            // vectorized weight fetch for softmax-att + dw bias
            const float* aP = &s_acw[c * 12];
            const float* bP = &s_acb[c * 12];
            const float* sP = &s_scb[c * 12];
            float4 awa = LD4(aP), awb = LD4(aP + 4);
            float4 aba = LD4(bP), abb = LD4(bP + 4);
            float4 sba = LD4(sP), sbb = LD4(sP + 4);
            float aw[9] = {awa.x, awa.y, awa.z, awa.w, awb.x, awb.y, awb.z, awb.w, aP[8]};
            float ab[9] = {aba.x, aba.y, aba.z, aba.w, abb.x, abb.y, abb.z, abb.w, bP[8]};
            float sb[9] = {sba.x, sba.y, sba.z, sba.w, sbb.x, sbb.y, sbb.z, sbb.w, sP[8]};

            float t0[9], t1[9];
            float sum0 = 0.f, sum1 = 0.f;
#pragma unroll
            for (int j = 0; j < 9; j++) {
                float e0 = __expf(fmaf(p0, aw[j], ab[j]));
                float e1 = __expf(fmaf(p1, aw[j], ab[j]));
                sum0 += e0;
                sum1 += e1;
                const float* wP = &s_scw[(c * 9 + j) * 12];
                float4 wA = LD4(wP), wB = LD4(wP + 4);
                float  w8 = wP[8];
                float d0 = n[0][0] * wA.x + n[0][1] * wA.y + n[0][2] * wA.z
                         + n[1][0] * wA.w + n[1][1] * wB.x + n[1][2] * wB.y
                         + n[2][0] * wB.z + n[2][1] * wB.w + n[2][2] * w8 + sb[j];
                float d1 = n[0][1] * wA.x + n[0][2] * wA.y + n[0][3] * wA.z
                         + n[1][1] * wA.w + n[1][2] * wB.x + n[1][3] * wB.y
                         + n[2][1] * wB.z + n[2][2] * wB.w + n[2][3] * w8 + sb[j];
                t0[j] = silu_(d0) * e0;
                t1[j] = silu_(d1) * e1;
            }
            float r0 = 1.f / sum0;
            float r1 = 1.f / sum1;

            // grouped projection (r0/r1 factored out of the j-sum)
#pragma unroll
            for (int oo = 0; oo < 16; oo++) {
                const float* oP = &s_ocw[(((og * 16 + oo) * 16) + cl) * 12];
                float4 oa = LD4(oP), ob4 = LD4(oP + 4);
                float  o8 = oP[8];
                float s0 = t0[0] * oa.x + t0[1] * oa.y + t0[2] * oa.z + t0[3] * oa.w
                         + t0[4] * ob4.x + t0[5] * ob4.y + t0[6] * ob4.z + t0[7] * ob4.w
                         + t0[8] * o8;
                float s1 = t1[0] * oa.x + t1[1] * oa.y + t1[2] * oa.z + t1[3] * oa.w
                         + t1[4] * ob4.x + t1[5] * ob4.y + t1[6] * ob4.z + t1[7] * ob4.w
                         + t1[8] * o8;
                acc0[oo] = fmaf(r0, s0, acc0[oo]);
                acc1[oo] = fmaf(r1, s1, acc1[oo]);
            }

            // fused 1x1: x_fgca contribution (x * channel scale)
            float scv = s_scale[c];
            float xs0 = n[1][1] * scv;
            float xs1 = n[1][2] * scv;
            const float4* wX = (const float4*)&s_wsT[(64 + c) * 32];
#pragma unroll
            for (int q = 0; q < 8; q++) {
                float4 wv = wX[q];
                FMA4(f0[q], wv, xs0);
                FMA4(f1[q], wv, xs1);
            }
        }

        // fused 1x1: x_rfa contribution for this group's 16 channels
#pragma unroll
        for (int oo = 0; oo < 16; oo++) {
            int o = og * 16 + oo;
            float y0 = silu_(fmaf(acc0[oo], s_bs[o], s_bb[o]));
            float y1 = silu_(fmaf(acc1[oo], s_bs[o], s_bb[o]));
            const float4* wY = (const float4*)&s_wsT[o * 32];
#pragma unroll
            for (int q = 0; q < 8; q++) {
                float4 wv = wY[q];
                FMA4(f0[q], wv, y0);
                FMA4(f1[q], wv, y1);
            }
        }
    }

    // epilogue: SiLU + store 32 output channels
    float* outp = out + (size_t)(b * 32) * NPIX + pix;
#pragma unroll
    for (int q = 0; q < 8; q++) {
        *(float2*)&outp[(size_t)(q * 4 + 0) * NPIX] = make_float2(silu_(f0[q].x), silu_(f1[q].x));
        *(float2*)&outp[(size_t)(q * 4 + 1) * NPIX] = make_float2(silu_(f0[q].y), silu_(f1[q].y));
        *(float2*)&outp[(size_t)(q * 4 + 2) * NPIX] = make_float2(silu_(f0[q].z), silu_(f1[q].z));
        *(float2*)&outp[(size_t)(q * 4 + 3) * NPIX] = make_float2(silu_(f0[q].w), silu_(f1[q].w));
    }
}

// ==================================================================================
extern "C" void kernel_launch(void* const* d_in, const int* in_sizes, int n_in,
                              void* d_out, int out_size)
{
    const float* x      = (const float*)d_in[0];
    const float* sc_w   = (const float*)d_in[1];
    const float* sc_b   = (const float*)d_in[2];
    const float* ac_w   = (const float*)d_in[3];
    const float* ac_b   = (const float*)d_in[4];
    const float* oc_w   = (const float*)d_in[5];
    const float* oc_b   = (const float*)d_in[6];
    const float* oc_bng = (const float*)d_in[7];
    const float* oc_bnb = (const float*)d_in[8];
    const float* oc_bnm = (const float*)d_in[9];
    const float* oc_bnv = (const float*)d_in[10];
    const float* ex_w   = (const float*)d_in[11];
    const float* ey_w   = (const float*)d_in[12];
    const float* ez_w   = (const float*)d_in[13];
    const float* ff_w   = (const float*)d_in[14];
    const float* ff_b   = (const float*)d_in[15];
    const float* g1_w   = (const float*)d_in[16];
    const float* g1_b   = (const float*)d_in[17];
    const float* g2_w   = (const float*)d_in[18];
    const float* g2_b   = (const float*)d_in[19];
    const float* fu_w   = (const float*)d_in[20];
    const float* fu_b   = (const float*)d_in[21];
    const float* fu_bng = (const float*)d_in[22];
    const float* fu_bnb = (const float*)d_in[23];
    const float* fu_bnm = (const float*)d_in[24];
    const float* fu_bnv = (const float*)d_in[25];

    fft_energy_kernel<<<BB * CC, 256>>>(x);
    gates_kernel<<<BB, 64>>>(ex_w, ey_w, ez_w, ff_w, ff_b, g1_w, g1_b, g2_w, g2_b);
    rfa_fuse_kernel<<<BB * 32, 64>>>(x, sc_w, sc_b, ac_w, ac_b, oc_w, oc_b,
                                     oc_bng, oc_bnb, oc_bnm, oc_bnv,
                                     fu_w, fu_b, fu_bng, fu_bnb, fu_bnm, fu_bnv,
                                     (float*)d_out);
}

// round 5
// speedup vs baseline: 2.4867x; 1.6602x over previous
#include <cuda_runtime.h>
#include <math.h>

#define BB   8
#define CC   64
#define OUTC 32
#define NPIX 4096   // 64*64

typedef unsigned long long u64;

// ---------------- scratch (static device globals; no allocation) ----------------
__device__ float g_mean[BB * CC];
__device__ float g_energy[BB * CC];
__device__ float g_scale[BB * CC];

__device__ __forceinline__ float sigm_(float v) { return __fdividef(1.f, 1.f + __expf(-v)); }
__device__ __forceinline__ float silu_(float v) { return v * __fdividef(1.f, 1.f + __expf(-v)); }

// ---------------- packed fp32x2 helpers (FFMA2 path, sm_100+) ----------------
__device__ __forceinline__ u64 pack2_(float lo, float hi) {
    u64 r; asm("mov.b64 %0, {%1, %2};" : "=l"(r) : "f"(lo), "f"(hi)); return r;
}
__device__ __forceinline__ u64 pack1_(float v) {
    u64 r; asm("mov.b64 %0, {%1, %1};" : "=l"(r) : "f"(v)); return r;
}
__device__ __forceinline__ void unpack2_(u64 p, float& lo, float& hi) {
    asm("mov.b64 {%0, %1}, %2;" : "=f"(lo), "=f"(hi) : "l"(p));
}
__device__ __forceinline__ u64 fma2_(u64 a, u64 b, u64 c) {
    u64 d; asm("fma.rn.f32x2 %0, %1, %2, %3;" : "=l"(d) : "l"(a), "l"(b), "l"(c)); return d;
}

// ==================================================================================
// Kernel 1: per-(b,c) 64x64 DFT magnitude mean + spatial mean.
// ==================================================================================
__device__ __forceinline__ void rot90_(float c, float s, int m, float& cv, float& sv)
{
    // angle offset m * pi/2:  m0:(c,s)  m1:(-s,c)  m2:(-c,-s)  m3:(s,-c)
    float cs = (m & 1) ? s : c;
    float sn = (m & 1) ? c : s;
    cv = (m == 1 || m == 2) ? -cs : cs;
    sv = (m >= 2) ? -sn : sn;
}

__global__ __launch_bounds__(256) void fft_energy_kernel(const float* __restrict__ x)
{
    __shared__ float xs[4096];
    __shared__ float Ar[2112];   // [n1][k2<=32], stride 33
    __shared__ float Ai[2112];
    __shared__ float ct[64], st[64];
    __shared__ float red[256];

    const int tid = threadIdx.x;
    const int bc  = blockIdx.x;

    if (tid < 64) {
        float sv, cv;
        sincosf(0.09817477042468103f * (float)tid, &sv, &cv);   // 2*pi/64 * tid
        ct[tid] = cv;
        st[tid] = sv;
    }

    const float* xp = x + (size_t)bc * NPIX;
    float lsum = 0.f;
    for (int i = tid; i < 4096; i += 256) {
        float v = xp[i];
        xs[i] = v;
        lsum += v;
    }
    red[tid] = lsum;
    __syncthreads();
    for (int s = 128; s > 0; s >>= 1) {
        if (tid < s) red[tid] += red[tid + s];
        __syncthreads();
    }
    if (tid == 0) g_mean[bc] = red[0] * (1.f / 4096.f);

    // ---- pass 1: A[n1][k2] = sum_n2 x[n1][n2] * e^{-i 2pi k2 n2/64}, k2 in [0,32]
    for (int t = tid; t < 528; t += 256) {
        int n1a = t / 33;
        int k2  = t - n1a * 33;
        float sd, cd;
        __sincosf(0.09817477042468103f * (float)k2, &sd, &cd);
        float cv = 1.f, sv = 0.f;
        float a0r = 0.f, a0i = 0.f, a1r = 0.f, a1i = 0.f;
        float a2r = 0.f, a2i = 0.f, a3r = 0.f, a3i = 0.f;
        const float* x0 = &xs[n1a * 64];
#pragma unroll 8
        for (int n2 = 0; n2 < 64; n2++) {
            float v0 = x0[n2];
            float v1 = x0[n2 + 1024];
            float v2 = x0[n2 + 2048];
            float v3 = x0[n2 + 3072];
            a0r += v0 * cv;  a0i -= v0 * sv;
            a1r += v1 * cv;  a1i -= v1 * sv;
            a2r += v2 * cv;  a2i -= v2 * sv;
            a3r += v3 * cv;  a3i -= v3 * sv;
            float ncv = cv * cd - sv * sd;
            float nsv = sv * cd + cv * sd;
            cv = ncv; sv = nsv;
        }
        Ar[n1a * 33 + k2]          = a0r;  Ai[n1a * 33 + k2]          = a0i;
        Ar[(n1a + 16) * 33 + k2]   = a1r;  Ai[(n1a + 16) * 33 + k2]   = a1i;
        Ar[(n1a + 32) * 33 + k2]   = a2r;  Ai[(n1a + 32) * 33 + k2]   = a2i;
        Ar[(n1a + 48) * 33 + k2]   = a3r;  Ai[(n1a + 48) * 33 + k2]   = a3i;
    }
    __syncthreads();

    // ---- pass 2: full unroll -> rot90 selects fold to compile-time sign flips
    float esum = 0.f;
    for (int t = tid; t < 528; t += 256) {
        int k1a = t / 33;
        int k2  = t - k1a * 33;
        float r0r = 0.f, r0i = 0.f, r1r = 0.f, r1i = 0.f;
        float r2r = 0.f, r2i = 0.f, r3r = 0.f, r3i = 0.f;
        int mm = 0;
#pragma unroll
        for (int n1 = 0; n1 < 64; n1++) {
            float ar = Ar[n1 * 33 + k2];
            float ai = Ai[n1 * 33 + k2];
            float c0 = ct[mm], s0 = st[mm];
            mm = (mm + k1a) & 63;
            r0r += ar * c0 + ai * s0;
            r0i += ai * c0 - ar * s0;
            const int m1 = n1 & 3;
            const int m2 = (n1 << 1) & 3;
            const int m3 = (m1 + m2) & 3;
            float cv, sv;
            rot90_(c0, s0, m1, cv, sv);
            r1r += ar * cv + ai * sv;  r1i += ai * cv - ar * sv;
            rot90_(c0, s0, m2, cv, sv);
            r2r += ar * cv + ai * sv;  r2i += ai * cv - ar * sv;
            rot90_(c0, s0, m3, cv, sv);
            r3r += ar * cv + ai * sv;  r3i += ai * cv - ar * sv;
        }
        float wgt = (k2 == 0 || k2 == 32) ? 1.f : 2.f;
        esum += wgt * (sqrtf(r0r * r0r + r0i * r0i) + sqrtf(r1r * r1r + r1i * r1i) +
                       sqrtf(r2r * r2r + r2i * r2i) + sqrtf(r3r * r3r + r3i * r3i));
    }
    __syncthreads();
    red[tid] = esum;
    __syncthreads();
    for (int s = 128; s > 0; s >>= 1) {
        if (tid < s) red[tid] += red[tid + s];
        __syncthreads();
    }
    if (tid == 0) g_energy[bc] = red[0] * (1.f / 4096.f);
}

// ==================================================================================
// Kernel 2: FGCA gate pipeline -> per-(b,c) channel scale. One block per batch.
// ==================================================================================
__global__ __launch_bounds__(64) void gates_kernel(
    const float* __restrict__ ex_w, const float* __restrict__ ey_w, const float* __restrict__ ez_w,
    const float* __restrict__ ff_w, const float* __restrict__ ff_b,
    const float* __restrict__ g1_w, const float* __restrict__ g1_b,
    const float* __restrict__ g2_w, const float* __restrict__ g2_b)
{
    const int b = blockIdx.x;
    const int c = threadIdx.x;

    __shared__ float se[64], smn[64], smy[64], smz[64];
    __shared__ float ax[64], ay[64], az[64], af[64], hv[16];

    se[c]  = g_energy[b * 64 + c];
    smn[c] = g_mean[b * 64 + c];
    __syncthreads();

    float e    = se[c];
    int   rank = 0;
#pragma unroll 16
    for (int c2 = 0; c2 < 64; c2++) {
        float e2 = se[c2];
        rank += (e2 > e) || (e2 == e && c2 < c);
    }
    float mask = (rank < 32) ? 1.f : 0.f;
    smy[c] = smn[c] * mask;
    smz[c] = smn[c] * (1.f - mask);
    __syncthreads();

    {
        float w0 = ex_w[0], w1 = ex_w[1], w2 = ex_w[2];
        float v = smn[c] * w1;
        if (c > 0)  v += smn[c - 1] * w0;
        if (c < 63) v += smn[c + 1] * w2;
        ax[c] = sigm_(v);
    }
    {
        float w0 = ey_w[0], w1 = ey_w[1], w2 = ey_w[2];
        float v = smy[c] * w1;
        if (c > 0)  v += smy[c - 1] * w0;
        if (c < 63) v += smy[c + 1] * w2;
        ay[c] = sigm_(v);
    }
    {
        float w0 = ez_w[0], w1 = ez_w[1], w2 = ez_w[2];
        float v = smz[c] * w1;
        if (c > 0)  v += smz[c - 1] * w0;
        if (c < 63) v += smz[c + 1] * w2;
        az[c] = sigm_(v);
    }
    __syncthreads();

    {
        int g = c >> 4;
        const float* src = (g < 2) ? ay : az;
        int base         = (g < 2) ? g * 32 : (g - 2) * 32;
        float s = ff_b[c];
#pragma unroll 8
        for (int j = 0; j < 32; j++) s += ff_w[c * 32 + j] * src[base + j];
        af[c] = s;
    }
    __syncthreads();

    if (c < 16) {
        float hsum = g1_b[c];
#pragma unroll 8
        for (int i = 0; i < 64; i++) hsum += g1_w[c * 128 + i] * af[i];
#pragma unroll 8
        for (int i = 0; i < 64; i++) hsum += g1_w[c * 128 + 64 + i] * ax[i];
        hv[c] = silu_(hsum);
    }
    __syncthreads();

    float gs = g2_b[c];
#pragma unroll
    for (int j = 0; j < 16; j++) gs += g2_w[c * 16 + j] * hv[j];
    float gg = sigm_(gs);

    g_scale[b * 64 + c] = gg * af[c] + (1.f - gg) * ax[c];
}

// ==================================================================================
// Kernel 3: RFA conv + FGCA apply + final 1x1 fuse + BN + SiLU, f32x2-packed.
// 128 threads/block, 2 px/thread, 256 px/block, grid = B*16 = 128 (single wave).
// dw-conv pairs the 2 pixels (duplicated (w,w) smem); projection + fuse pair
// adjacent output channels (ulonglong2 weight loads, no duplication).
// ==================================================================================
__global__ __launch_bounds__(128) void rfa_fuse_kernel(
    const float* __restrict__ x,
    const float* __restrict__ sc_w, const float* __restrict__ sc_b,
    const float* __restrict__ ac_w, const float* __restrict__ ac_b,
    const float* __restrict__ oc_w, const float* __restrict__ oc_b,
    const float* __restrict__ bng, const float* __restrict__ bnb,
    const float* __restrict__ bnm, const float* __restrict__ bnv,
    const float* __restrict__ fu_w, const float* __restrict__ fu_b,
    const float* __restrict__ fbng, const float* __restrict__ fbnb,
    const float* __restrict__ fbnm, const float* __restrict__ fbnv,
    float* __restrict__ out)
{
    __shared__ __align__(16) float2 s_scw2[5760];   // (c*9+j)*10 + tap : (w,w) pairs
    __shared__ __align__(16) float  s_ocwT[9216];   // (cl*9+j)*64 + o   : transposed
    __shared__ __align__(16) float  s_scb[768];     // c*12 + j
    __shared__ __align__(16) float  s_acw[768];
    __shared__ __align__(16) float  s_acb[768];
    __shared__ __align__(16) float  s_wsT[4096];    // [cc 0..127][o 0..31]
    __shared__ __align__(16) float  s_bf[32];
    __shared__ __align__(16) float  s_ob[64], s_bs[64], s_bb[64];
    __shared__ __align__(16) float  s_scale[64], s_s32[32];

    const int tid   = threadIdx.x;
    const int b     = blockIdx.x >> 4;
    const int chunk = blockIdx.x & 15;

    for (int i = tid; i < 5184; i += 128) {
        int g = i / 9, j = i - g * 9;
        float wv = sc_w[i];
        s_scw2[g * 10 + j] = make_float2(wv, wv);
    }
    for (int i = tid; i < 576; i += 128) {
        int cc = i / 9, j = i - cc * 9;
        s_scb[cc * 12 + j] = sc_b[i];
        s_acw[cc * 12 + j] = ac_w[i];
        s_acb[cc * 12 + j] = ac_b[i];
    }
    for (int i = tid; i < 9216; i += 128) {
        int o = i / 144, r = i - o * 144;
        int cl = r / 9,  j = r - cl * 9;
        s_ocwT[(cl * 9 + j) * 64 + o] = oc_w[i];
    }
    if (tid < 64) {
        float s = bng[tid] * rsqrtf(bnv[tid] + 1e-5f);
        s_bs[tid]    = s;
        s_bb[tid]    = bnb[tid] - bnm[tid] * s;
        s_ob[tid]    = oc_b[tid];
        s_scale[tid] = g_scale[b * 64 + tid];
    }
    if (tid < 32) {
        float s = fbng[tid] * rsqrtf(fbnv[tid] + 1e-5f);
        s_s32[tid] = s;
        s_bf[tid]  = fu_b[tid] * s + fbnb[tid] - fbnm[tid] * s;
    }
    __syncthreads();
    for (int i = tid; i < 4096; i += 128) {
        int o = i & 31, cc = i >> 5;
        s_wsT[i] = fu_w[o * 128 + cc] * s_s32[o];
    }
    __syncthreads();

    const int pix = chunk * 256 + tid * 2;
    const int h   = pix >> 6;
    const int w0  = pix & 63;
    const float* xb = x + (size_t)b * CC * NPIX;
    const bool has_l = (w0 > 0);
    const bool has_r = (w0 < 62);

    // fused 1x1 accumulators: pairs over adjacent OUTPUT channels; px0 and px1 sets
    u64 fp0[16], fp1[16];
#pragma unroll
    for (int q = 0; q < 16; q++) {
        fp0[q] = *(const u64*)&s_bf[q * 2];
        fp1[q] = fp0[q];
    }

    for (int og = 0; og < 4; og++) {
        // projection accumulators: pairs over adjacent outputs within group
        u64 ap0[8], ap1[8];
#pragma unroll
        for (int q = 0; q < 8; q++) {
            ap0[q] = *(const u64*)&s_ob[og * 16 + q * 2];
            ap1[q] = ap0[q];
        }

        for (int cl = 0; cl < 16; cl++) {
            const int c = og * 16 + cl;
            const float* xc = xb + (size_t)c * NPIX;

            float n[3][4];
#pragma unroll
            for (int r = 0; r < 3; r++) {
                int   hh = h + r - 1;
                float v0 = 0.f, v1 = 0.f, v2 = 0.f, v3 = 0.f;
                if (hh >= 0 && hh < 64) {
                    const float* rowp = xc + hh * 64;
                    float2 mid = *(const float2*)(rowp + w0);
                    v1 = mid.x; v2 = mid.y;
                    if (has_l) v0 = rowp[w0 - 1];
                    if (has_r) v3 = rowp[w0 + 2];
                }
                n[r][0] = v0; n[r][1] = v1; n[r][2] = v2; n[r][3] = v3;
            }

            float p0 = 0.f, p1 = 0.f;
#pragma unroll
            for (int r = 0; r < 3; r++) {
                p0 += n[r][0] + n[r][1] + n[r][2];
                p1 += n[r][1] + n[r][2] + n[r][3];
            }
            p0 *= (1.f / 9.f);
            p1 *= (1.f / 9.f);

            // packed neighborhood: (px0 tap, px1 tap)
            u64 np[9];
#pragma unroll
            for (int r = 0; r < 3; r++) {
                np[r * 3 + 0] = pack2_(n[r][0], n[r][1]);
                np[r * 3 + 1] = pack2_(n[r][1], n[r][2]);
                np[r * 3 + 2] = pack2_(n[r][2], n[r][3]);
            }

            // softmax logits + max
            float a0[9], a1[9];
            float m0 = -1e30f, m1 = -1e30f;
#pragma unroll
            for (int j = 0; j < 9; j++) {
                float awv = s_acw[c * 12 + j];
                float abv = s_acb[c * 12 + j];
                a0[j] = fmaf(p0, awv, abv);
                a1[j] = fmaf(p1, awv, abv);
                m0 = fmaxf(m0, a0[j]);
                m1 = fmaxf(m1, a1[j]);
            }

            // dw conv (packed over px) + silu + softmax numerator
            float t0[9], t1[9];
            float sum0 = 0.f, sum1 = 0.f;
#pragma unroll
            for (int j = 0; j < 9; j++) {
                const u64* wp = (const u64*)&s_scw2[(c * 9 + j) * 10];
                ulonglong2 wv01 = ((const ulonglong2*)wp)[0];
                ulonglong2 wv23 = ((const ulonglong2*)wp)[1];
                ulonglong2 wv45 = ((const ulonglong2*)wp)[2];
                ulonglong2 wv67 = ((const ulonglong2*)wp)[3];
                u64        wv8  = wp[8];
                u64 dp = pack1_(s_scb[c * 12 + j]);
                dp = fma2_(np[0], wv01.x, dp);
                dp = fma2_(np[1], wv01.y, dp);
                dp = fma2_(np[2], wv23.x, dp);
                dp = fma2_(np[3], wv23.y, dp);
                dp = fma2_(np[4], wv45.x, dp);
                dp = fma2_(np[5], wv45.y, dp);
                dp = fma2_(np[6], wv67.x, dp);
                dp = fma2_(np[7], wv67.y, dp);
                dp = fma2_(np[8], wv8,    dp);
                float d0, d1;
                unpack2_(dp, d0, d1);
                float e0 = __expf(a0[j] - m0);
                float e1 = __expf(a1[j] - m1);
                sum0 += e0;
                sum1 += e1;
                t0[j] = silu_(d0) * e0;
                t1[j] = silu_(d1) * e1;
            }
            float r0 = __fdividef(1.f, sum0);
            float r1 = __fdividef(1.f, sum1);

            // grouped projection: packed over output pairs
#pragma unroll
            for (int j = 0; j < 9; j++) {
                const ulonglong2* op = (const ulonglong2*)&s_ocwT[(cl * 9 + j) * 64 + og * 16];
                ulonglong2 w01 = op[0], w23 = op[1], w45 = op[2], w67 = op[3];
                u64 tp0 = pack1_(t0[j] * r0);
                u64 tp1 = pack1_(t1[j] * r1);
                ap0[0] = fma2_(w01.x, tp0, ap0[0]);  ap1[0] = fma2_(w01.x, tp1, ap1[0]);
                ap0[1] = fma2_(w01.y, tp0, ap0[1]);  ap1[1] = fma2_(w01.y, tp1, ap1[1]);
                ap0[2] = fma2_(w23.x, tp0, ap0[2]);  ap1[2] = fma2_(w23.x, tp1, ap1[2]);
                ap0[3] = fma2_(w23.y, tp0, ap0[3]);  ap1[3] = fma2_(w23.y, tp1, ap1[3]);
                ap0[4] = fma2_(w45.x, tp0, ap0[4]);  ap1[4] = fma2_(w45.x, tp1, ap1[4]);
                ap0[5] = fma2_(w45.y, tp0, ap0[5]);  ap1[5] = fma2_(w45.y, tp1, ap1[5]);
                ap0[6] = fma2_(w67.x, tp0, ap0[6]);  ap1[6] = fma2_(w67.x, tp1, ap1[6]);
                ap0[7] = fma2_(w67.y, tp0, ap0[7]);  ap1[7] = fma2_(w67.y, tp1, ap1[7]);
            }

            // fused 1x1: x_fgca contribution (x center * channel scale)
            float scv = s_scale[c];
            u64 xp0 = pack1_(n[1][1] * scv);
            u64 xp1 = pack1_(n[1][2] * scv);
            const ulonglong2* wx = (const ulonglong2*)&s_wsT[(64 + c) * 32];
#pragma unroll
            for (int q = 0; q < 8; q++) {
                ulonglong2 wv = wx[q];
                fp0[q * 2 + 0] = fma2_(wv.x, xp0, fp0[q * 2 + 0]);
                fp0[q * 2 + 1] = fma2_(wv.y, xp0, fp0[q * 2 + 1]);
                fp1[q * 2 + 0] = fma2_(wv.x, xp1, fp1[q * 2 + 0]);
                fp1[q * 2 + 1] = fma2_(wv.y, xp1, fp1[q * 2 + 1]);
            }
        }

        // BN + SiLU on rfa outputs, then fused-1x1 x_rfa contribution
#pragma unroll
        for (int q = 0; q < 8; q++) {
            int o = og * 16 + q * 2;
            u64 bsp = *(const u64*)&s_bs[o];
            u64 bbp = *(const u64*)&s_bb[o];
            u64 z0 = fma2_(ap0[q], bsp, bbp);
            u64 z1 = fma2_(ap1[q], bsp, bbp);
            float ya, yb, yc, yd;
            unpack2_(z0, ya, yb);   // px0: outputs o, o+1
            unpack2_(z1, yc, yd);   // px1: outputs o, o+1
            u64 pya = pack1_(silu_(ya));
            u64 pyb = pack1_(silu_(yb));
            u64 pyc = pack1_(silu_(yc));
            u64 pyd = pack1_(silu_(yd));
            const ulonglong2* w0p = (const ulonglong2*)&s_wsT[o * 32];
            const ulonglong2* w1p = (const ulonglong2*)&s_wsT[(o + 1) * 32];
#pragma unroll
            for (int q2 = 0; q2 < 8; q2++) {
                ulonglong2 wa = w0p[q2];
                ulonglong2 wb = w1p[q2];
                fp0[q2 * 2 + 0] = fma2_(wa.x, pya, fp0[q2 * 2 + 0]);
                fp0[q2 * 2 + 1] = fma2_(wa.y, pya, fp0[q2 * 2 + 1]);
                fp0[q2 * 2 + 0] = fma2_(wb.x, pyb, fp0[q2 * 2 + 0]);
                fp0[q2 * 2 + 1] = fma2_(wb.y, pyb, fp0[q2 * 2 + 1]);
                fp1[q2 * 2 + 0] = fma2_(wa.x, pyc, fp1[q2 * 2 + 0]);
                fp1[q2 * 2 + 1] = fma2_(wa.y, pyc, fp1[q2 * 2 + 1]);
                fp1[q2 * 2 + 0] = fma2_(wb.x, pyd, fp1[q2 * 2 + 0]);
                fp1[q2 * 2 + 1] = fma2_(wb.y, pyd, fp1[q2 * 2 + 1]);
            }
        }
    }

    // epilogue: SiLU + store; fp pairs = adjacent output channels
    float* outp = out + (size_t)(b * 32) * NPIX + pix;
#pragma unroll
    for (int q = 0; q < 16; q++) {
        float ea, eb, fa, fb;
        unpack2_(fp0[q], ea, eb);   // px0: outputs 2q, 2q+1
        unpack2_(fp1[q], fa, fb);   // px1
        *(float2*)&outp[(size_t)(2 * q + 0) * NPIX] = make_float2(silu_(ea), silu_(fa));
        *(float2*)&outp[(size_t)(2 * q + 1) * NPIX] = make_float2(silu_(eb), silu_(fb));
    }
}

// ==================================================================================
extern "C" void kernel_launch(void* const* d_in, const int* in_sizes, int n_in,
                              void* d_out, int out_size)
{
    const float* x      = (const float*)d_in[0];
    const float* sc_w   = (const float*)d_in[1];
    const float* sc_b   = (const float*)d_in[2];
    const float* ac_w   = (const float*)d_in[3];
    const float* ac_b   = (const float*)d_in[4];
    const float* oc_w   = (const float*)d_in[5];
    const float* oc_b   = (const float*)d_in[6];
    const float* oc_bng = (const float*)d_in[7];
    const float* oc_bnb = (const float*)d_in[8];
    const float* oc_bnm = (const float*)d_in[9];
    const float* oc_bnv = (const float*)d_in[10];
    const float* ex_w   = (const float*)d_in[11];
    const float* ey_w   = (const float*)d_in[12];
    const float* ez_w   = (const float*)d_in[13];
    const float* ff_w   = (const float*)d_in[14];
    const float* ff_b   = (const float*)d_in[15];
    const float* g1_w   = (const float*)d_in[16];
    const float* g1_b   = (const float*)d_in[17];
    const float* g2_w   = (const float*)d_in[18];
    const float* g2_b   = (const float*)d_in[19];
    const float* fu_w   = (const float*)d_in[20];
    const float* fu_b   = (const float*)d_in[21];
    const float* fu_bng = (const float*)d_in[22];
    const float* fu_bnb = (const float*)d_in[23];
    const float* fu_bnm = (const float*)d_in[24];
    const float* fu_bnv = (const float*)d_in[25];

    fft_energy_kernel<<<BB * CC, 256>>>(x);
    gates_kernel<<<BB, 64>>>(ex_w, ey_w, ez_w, ff_w, ff_b, g1_w, g1_b, g2_w, g2_b);
    rfa_fuse_kernel<<<BB * 16, 128>>>(x, sc_w, sc_b, ac_w, ac_b, oc_w, oc_b,
                                      oc_bng, oc_bnb, oc_bnm, oc_bnv,
                                      fu_w, fu_b, fu_bng, fu_bnb, fu_bnm, fu_bnv,
                                      (float*)d_out);
}

// round 8
// speedup vs baseline: 2.6115x; 1.0502x over previous
#include <cuda_runtime.h>
#include <math.h>

#define BB   8
#define CC   64
#define OUTC 32
#define NPIX 4096   // 64*64

typedef unsigned long long u64;

// ---------------- scratch (static device globals; no allocation) ----------------
__device__ float g_mean[BB * CC];
__device__ float g_energy[BB * CC];
__device__ float g_scale[BB * CC];

__device__ __forceinline__ float sigm_(float v) { return __fdividef(1.f, 1.f + __expf(-v)); }
__device__ __forceinline__ float silu_(float v) { return v * __fdividef(1.f, 1.f + __expf(-v)); }

// ---------------- packed fp32x2 helpers (FFMA2 path, sm_100+) ----------------
__device__ __forceinline__ u64 pack2_(float lo, float hi) {
    u64 r; asm("mov.b64 %0, {%1, %2};" : "=l"(r) : "f"(lo), "f"(hi)); return r;
}
__device__ __forceinline__ u64 pack1_(float v) {
    u64 r; asm("mov.b64 %0, {%1, %1};" : "=l"(r) : "f"(v)); return r;
}
__device__ __forceinline__ void unpack2_(u64 p, float& lo, float& hi) {
    asm("mov.b64 {%0, %1}, %2;" : "=f"(lo), "=f"(hi) : "l"(p));
}
__device__ __forceinline__ u64 fma2_(u64 a, u64 b, u64 c) {
    u64 d; asm("fma.rn.f32x2 %0, %1, %2, %3;" : "=l"(d) : "l"(a), "l"(b), "l"(c)); return d;
}

// quadrant-rotated complex accumulate: acc += rot90^m(c0,s0) applied to (ar,ai)
// contribution = c*F + s*G with (F,G) selected from {A,S,nA,nS}; m compile-time.
__device__ __forceinline__ void contrib_(u64& acc, int m, u64 A, u64 S, u64 nA, u64 nS,
                                         u64 pc, u64 ps) {
    u64 f, g;
    switch (m & 3) {
        case 0:  f = A;  g = S;  break;
        case 1:  f = S;  g = nA; break;
        case 2:  f = nA; g = nS; break;
        default: f = nS; g = A;  break;
    }
    acc = fma2_(f, pc, acc);
    acc = fma2_(g, ps, acc);
}

// ==================================================================================
// Kernel 1: per-(b,c) 64x64 DFT magnitude mean + spatial mean.
// Main tasks are 512 (k2 in [0,32) handled packed); k2=32 column (twiddle=(-1)^n)
// handled by a 64-thread side phase. Hermitian: interior k2 counted twice.
// ==================================================================================
__global__ __launch_bounds__(256) void fft_energy_kernel(const float* __restrict__ x)
{
    __shared__ float  xs[4096];
    __shared__ float2 As[2112];          // [n1][k2 0..32] (ar, ai), stride 33
    __shared__ float  ct[64], st[64];
    __shared__ float  red[256];

    const int tid = threadIdx.x;
    const int bc  = blockIdx.x;

    if (tid < 64) {
        float sv, cv;
        sincosf(0.09817477042468103f * (float)tid, &sv, &cv);   // 2*pi/64 * tid
        ct[tid] = cv;
        st[tid] = sv;
    }

    const float* xp = x + (size_t)bc * NPIX;
    float lsum = 0.f;
    for (int i = tid; i < 4096; i += 256) {
        float v = xp[i];
        xs[i] = v;
        lsum += v;
    }
    red[tid] = lsum;
    __syncthreads();
    for (int s = 128; s > 0; s >>= 1) {
        if (tid < s) red[tid] += red[tid + s];
        __syncthreads();
    }
    if (tid == 0) g_mean[bc] = red[0] * (1.f / 4096.f);

    // ---- pass 1 main: k2 in [0,32), 512 tasks = 2 clean rounds, packed rows (0,1),(2,3)
    for (int t = tid; t < 512; t += 256) {
        int n1a = t >> 5;
        int k2  = t & 31;
        float sd, cd;
        __sincosf(0.09817477042468103f * (float)k2, &sd, &cd);
        float cv = 1.f, sv = 0.f;
        u64 aR01 = 0ull, aI01 = 0ull, aR23 = 0ull, aI23 = 0ull;
        const float* x0 = &xs[n1a * 64];
#pragma unroll 4
        for (int n2b = 0; n2b < 64; n2b += 4) {
            float4 q0 = *(const float4*)&x0[n2b];
            float4 q1 = *(const float4*)&x0[n2b + 1024];
            float4 q2 = *(const float4*)&x0[n2b + 2048];
            float4 q3 = *(const float4*)&x0[n2b + 3072];
#pragma unroll
            for (int u = 0; u < 4; u++) {
                float v0 = (u == 0) ? q0.x : (u == 1) ? q0.y : (u == 2) ? q0.z : q0.w;
                float v1 = (u == 0) ? q1.x : (u == 1) ? q1.y : (u == 2) ? q1.z : q1.w;
                float v2 = (u == 0) ? q2.x : (u == 1) ? q2.y : (u == 2) ? q2.z : q2.w;
                float v3 = (u == 0) ? q3.x : (u == 1) ? q3.y : (u == 2) ? q3.z : q3.w;
                u64 v01 = pack2_(v0, v1);
                u64 v23 = pack2_(v2, v3);
                u64 pc  = pack1_(cv);
                u64 pns = pack1_(-sv);
                aR01 = fma2_(v01, pc, aR01);
                aI01 = fma2_(v01, pns, aI01);
                aR23 = fma2_(v23, pc, aR23);
                aI23 = fma2_(v23, pns, aI23);
                float ncv = cv * cd - sv * sd;
                float nsv = sv * cd + cv * sd;
                cv = ncv; sv = nsv;
            }
        }
        float a0r, a1r, a0i, a1i, a2r, a3r, a2i, a3i;
        unpack2_(aR01, a0r, a1r);
        unpack2_(aI01, a0i, a1i);
        unpack2_(aR23, a2r, a3r);
        unpack2_(aI23, a2i, a3i);
        As[n1a * 33 + k2]        = make_float2(a0r, a0i);
        As[(n1a + 16) * 33 + k2] = make_float2(a1r, a1i);
        As[(n1a + 32) * 33 + k2] = make_float2(a2r, a2i);
        As[(n1a + 48) * 33 + k2] = make_float2(a3r, a3i);
    }
    // ---- pass 1 side: k2 = 32, twiddle = (-1)^n2, purely real
    if (tid < 64) {
        const float* x0 = &xs[tid * 64];
        float s = 0.f;
#pragma unroll 4
        for (int n2b = 0; n2b < 64; n2b += 4) {
            float4 q = *(const float4*)&x0[n2b];
            s += q.x - q.y + q.z - q.w;
        }
        As[tid * 33 + 32] = make_float2(s, 0.f);
    }
    __syncthreads();

    // ---- pass 2 main: k2 in [0,32), packed quadrant trick over 4 k1-rows
    float esum = 0.f;
    for (int t = tid; t < 512; t += 256) {
        int k1a = t >> 5;
        int k2  = t & 31;
        u64 r0 = 0ull, r1 = 0ull, r2 = 0ull, r3 = 0ull;   // each = (rr, ri)
        int mm = 0;
        for (int n1b = 0; n1b < 64; n1b += 16) {
#pragma unroll
            for (int u = 0; u < 16; u++) {
                float2 A2 = As[(n1b + u) * 33 + k2];
                float ar = A2.x, ai = A2.y;
                float c0 = ct[mm], s0 = st[mm];
                mm = (mm + k1a) & 63;
                u64 A  = pack2_(ar, ai);
                u64 S  = pack2_(ai, -ar);
                u64 nA = pack2_(-ar, -ai);
                u64 nS = pack2_(-ai, ar);
                u64 pc = pack1_(c0);
                u64 ps = pack1_(s0);
                // quarter-turn count for row r is (r*u)&3 since n1b is a multiple of 16
                contrib_(r0, 0,           A, S, nA, nS, pc, ps);
                contrib_(r1, u & 3,       A, S, nA, nS, pc, ps);
                contrib_(r2, (2 * u) & 3, A, S, nA, nS, pc, ps);
                contrib_(r3, (3 * u) & 3, A, S, nA, nS, pc, ps);
            }
        }
        float w0r, w0i, w1r, w1i, w2r, w2i, w3r, w3i;
        unpack2_(r0, w0r, w0i);
        unpack2_(r1, w1r, w1i);
        unpack2_(r2, w2r, w2i);
        unpack2_(r3, w3r, w3i);
        float wgt = (k2 == 0) ? 1.f : 2.f;
        esum += wgt * (sqrtf(w0r * w0r + w0i * w0i) + sqrtf(w1r * w1r + w1i * w1i) +
                       sqrtf(w2r * w2r + w2i * w2i) + sqrtf(w3r * w3r + w3i * w3i));
    }
    // ---- pass 2 side: k2 = 32 column (A imag = 0)
    if (tid < 64) {
        float sd, cd;
        __sincosf(0.09817477042468103f * (float)tid, &sd, &cd);
        float cv = 1.f, sv = 0.f;
        float rr = 0.f, ri = 0.f;
#pragma unroll 8
        for (int n1 = 0; n1 < 64; n1++) {
            float ar = As[n1 * 33 + 32].x;
            rr += ar * cv;
            ri -= ar * sv;
            float ncv = cv * cd - sv * sd;
            float nsv = sv * cd + cv * sd;
            cv = ncv; sv = nsv;
        }
        esum += sqrtf(rr * rr + ri * ri);
    }
    __syncthreads();
    red[tid] = esum;
    __syncthreads();
    for (int s = 128; s > 0; s >>= 1) {
        if (tid < s) red[tid] += red[tid + s];
        __syncthreads();
    }
    if (tid == 0) g_energy[bc] = red[0] * (1.f / 4096.f);
}

// ==================================================================================
// Kernel 2: FGCA gate pipeline -> per-(b,c) channel scale. One block per batch.
// ==================================================================================
__global__ __launch_bounds__(64) void gates_kernel(
    const float* __restrict__ ex_w, const float* __restrict__ ey_w, const float* __restrict__ ez_w,
    const float* __restrict__ ff_w, const float* __restrict__ ff_b,
    const float* __restrict__ g1_w, const float* __restrict__ g1_b,
    const float* __restrict__ g2_w, const float* __restrict__ g2_b)
{
    const int b = blockIdx.x;
    const int c = threadIdx.x;

    __shared__ float se[64], smn[64], smy[64], smz[64];
    __shared__ float ax[64], ay[64], az[64], af[64], hv[16];

    se[c]  = g_energy[b * 64 + c];
    smn[c] = g_mean[b * 64 + c];
    __syncthreads();

    float e    = se[c];
    int   rank = 0;
#pragma unroll 16
    for (int c2 = 0; c2 < 64; c2++) {
        float e2 = se[c2];
        rank += (e2 > e) || (e2 == e && c2 < c);
    }
    float mask = (rank < 32) ? 1.f : 0.f;
    smy[c] = smn[c] * mask;
    smz[c] = smn[c] * (1.f - mask);
    __syncthreads();

    {
        float w0 = ex_w[0], w1 = ex_w[1], w2 = ex_w[2];
        float v = smn[c] * w1;
        if (c > 0)  v += smn[c - 1] * w0;
        if (c < 63) v += smn[c + 1] * w2;
        ax[c] = sigm_(v);
    }
    {
        float w0 = ey_w[0], w1 = ey_w[1], w2 = ey_w[2];
        float v = smy[c] * w1;
        if (c > 0)  v += smy[c - 1] * w0;
        if (c < 63) v += smy[c + 1] * w2;
        ay[c] = sigm_(v);
    }
    {
        float w0 = ez_w[0], w1 = ez_w[1], w2 = ez_w[2];
        float v = smz[c] * w1;
        if (c > 0)  v += smz[c - 1] * w0;
        if (c < 63) v += smz[c + 1] * w2;
        az[c] = sigm_(v);
    }
    __syncthreads();

    {
        int g = c >> 4;
        const float* src = (g < 2) ? ay : az;
        int base         = (g < 2) ? g * 32 : (g - 2) * 32;
        float s = ff_b[c];
#pragma unroll 8
        for (int j = 0; j < 32; j++) s += ff_w[c * 32 + j] * src[base + j];
        af[c] = s;
    }
    __syncthreads();

    if (c < 16) {
        float hsum = g1_b[c];
#pragma unroll 8
        for (int i = 0; i < 64; i++) hsum += g1_w[c * 128 + i] * af[i];
#pragma unroll 8
        for (int i = 0; i < 64; i++) hsum += g1_w[c * 128 + 64 + i] * ax[i];
        hv[c] = silu_(hsum);
    }
    __syncthreads();

    float gs = g2_b[c];
#pragma unroll
    for (int j = 0; j < 16; j++) gs += g2_w[c * 16 + j] * hv[j];
    float gg = sigm_(gs);

    g_scale[b * 64 + c] = gg * af[c] + (1.f - gg) * ax[c];
}

// ==================================================================================
// Kernel 3: RFA conv + FGCA apply + final 1x1 fuse + BN + SiLU, f32x2-packed.
// 256 threads/block, 1 px/thread (2 warps/SMSP for latency hiding), grid = B*16.
// dw-conv pairs RF positions j (weights (w_j, w_j+1) per tap); projection and
// fused 1x1 pair adjacent output channels.
// ==================================================================================
__global__ __launch_bounds__(256) void rfa_fuse_kernel(
    const float* __restrict__ x,
    const float* __restrict__ sc_w, const float* __restrict__ sc_b,
    const float* __restrict__ ac_w, const float* __restrict__ ac_b,
    const float* __restrict__ oc_w, const float* __restrict__ oc_b,
    const float* __restrict__ bng, const float* __restrict__ bnb,
    const float* __restrict__ bnm, const float* __restrict__ bnv,
    const float* __restrict__ fu_w, const float* __restrict__ fu_b,
    const float* __restrict__ fbng, const float* __restrict__ fbnb,
    const float* __restrict__ fbnm, const float* __restrict__ fbnv,
    float* __restrict__ out)
{
    __shared__ __align__(16) float2 s_scw2[3456];   // [(c*9+tap)*6 + jp] = (w[c,2jp,tap], w[c,2jp+1,tap])
    __shared__ __align__(16) float2 s_scbp[384];    // [c*6+jp] dw bias pairs
    __shared__ __align__(16) float2 s_acwp[384];    // [c*6+jp] att weight pairs
    __shared__ __align__(16) float2 s_acbp[384];    // [c*6+jp] att bias pairs
    __shared__ __align__(16) float  s_ocwT[9216];   // [(cl*9+j)*64 + o]
    __shared__ __align__(16) float  s_wsT[4096];    // [cc 0..127][o 0..31] = fu_w[o][cc]*bnS[o]
    __shared__ __align__(16) float  s_bf[32];
    __shared__ __align__(16) float  s_ob[64], s_bs[64], s_bb[64];
    __shared__ __align__(16) float  s_scale[64], s_s32[32];

    const int tid   = threadIdx.x;
    const int b     = blockIdx.x >> 4;
    const int chunk = blockIdx.x & 15;

    // ---- stage weights
    for (int i = tid; i < 64 * 9 * 5; i += 256) {
        int c2  = i / 45;
        int r   = i - c2 * 45;
        int tap = r / 5;
        int jp  = r - tap * 5;
        int j0  = jp * 2;
        int j1  = (jp == 4) ? 8 : j0 + 1;
        s_scw2[(c2 * 9 + tap) * 6 + jp] =
            make_float2(sc_w[(c2 * 9 + j0) * 9 + tap], sc_w[(c2 * 9 + j1) * 9 + tap]);
    }
    for (int i = tid; i < 64 * 5; i += 256) {
        int c2 = i / 5, jp = i - c2 * 5;
        int j0 = jp * 2;
        int j1 = (jp == 4) ? 8 : j0 + 1;
        s_scbp[c2 * 6 + jp] = make_float2(sc_b[c2 * 9 + j0], sc_b[c2 * 9 + j1]);
        s_acwp[c2 * 6 + jp] = make_float2(ac_w[c2 * 9 + j0], ac_w[c2 * 9 + j1]);
        s_acbp[c2 * 6 + jp] = make_float2(ac_b[c2 * 9 + j0], ac_b[c2 * 9 + j1]);
    }
    for (int i = tid; i < 9216; i += 256) {
        int o = i / 144, r = i - o * 144;
        int cl = r / 9,  j = r - cl * 9;
        s_ocwT[(cl * 9 + j) * 64 + o] = oc_w[i];
    }
    if (tid < 64) {
        float s = bng[tid] * rsqrtf(bnv[tid] + 1e-5f);
        s_bs[tid]    = s;
        s_bb[tid]    = bnb[tid] - bnm[tid] * s;
        s_ob[tid]    = oc_b[tid];
        s_scale[tid] = g_scale[b * 64 + tid];
    }
    if (tid < 32) {
        float s = fbng[tid] * rsqrtf(fbnv[tid] + 1e-5f);
        s_s32[tid] = s;
        s_bf[tid]  = fu_b[tid] * s + fbnb[tid] - fbnm[tid] * s;
    }
    __syncthreads();
    for (int i = tid; i < 4096; i += 256) {
        int o = i & 31, cc = i >> 5;
        s_wsT[i] = fu_w[o * 128 + cc] * s_s32[o];
    }
    __syncthreads();

    const int pix = chunk * 256 + tid;
    const int h   = pix >> 6;
    const int w0  = pix & 63;
    const float* xb = x + (size_t)b * CC * NPIX;
    const bool has_l = (w0 > 0);
    const bool has_r = (w0 < 63);

    // fused 1x1 accumulators: pairs of adjacent output channels
    u64 fp[16];
#pragma unroll
    for (int q = 0; q < 16; q++) fp[q] = *(const u64*)&s_bf[q * 2];

    for (int og = 0; og < 4; og++) {
        u64 ap[8];
#pragma unroll
        for (int q = 0; q < 8; q++) ap[q] = *(const u64*)&s_ob[og * 16 + q * 2];

        for (int cl = 0; cl < 16; cl++) {
            const int c = og * 16 + cl;
            const float* xc = xb + (size_t)c * NPIX;

            // 3x3 neighborhood (zero padded)
            float n[9];
#pragma unroll
            for (int r = 0; r < 3; r++) {
                int   hh = h + r - 1;
                float v0 = 0.f, v1 = 0.f, v2 = 0.f;
                if (hh >= 0 && hh < 64) {
                    const float* rowp = xc + hh * 64;
                    v1 = rowp[w0];
                    if (has_l) v0 = rowp[w0 - 1];
                    if (has_r) v2 = rowp[w0 + 1];
                }
                n[r * 3 + 0] = v0; n[r * 3 + 1] = v1; n[r * 3 + 2] = v2;
            }

            float p = (n[0] + n[1] + n[2] + n[3] + n[4] + n[5] + n[6] + n[7] + n[8]) * (1.f / 9.f);

            // softmax logits (packed pairs)
            u64 pp = pack1_(p);
            float a[9];
            {
                const u64* wq = (const u64*)&s_acwp[c * 6];
                const u64* bq = (const u64*)&s_acbp[c * 6];
                float hi_dummy;
#pragma unroll
                for (int jp = 0; jp < 4; jp++) {
                    u64 lg = fma2_(pp, wq[jp], bq[jp]);
                    unpack2_(lg, a[2 * jp], a[2 * jp + 1]);
                }
                u64 lg4 = fma2_(pp, wq[4], bq[4]);
                unpack2_(lg4, a[8], hi_dummy);
            }
            float mx = a[0];
#pragma unroll
            for (int j = 1; j < 9; j++) mx = fmaxf(mx, a[j]);

            // dw conv over taps, RF positions packed in pairs
            u64 dp[5];
            {
                const u64* bq = (const u64*)&s_scbp[c * 6];
#pragma unroll
                for (int jp = 0; jp < 5; jp++) dp[jp] = bq[jp];
            }
#pragma unroll
            for (int tap = 0; tap < 9; tap++) {
                u64 nv = pack1_(n[tap]);
                const u64* wp = (const u64*)&s_scw2[(c * 9 + tap) * 6];
                ulonglong2 w01 = ((const ulonglong2*)wp)[0];
                ulonglong2 w23 = ((const ulonglong2*)wp)[1];
                u64        w4  = wp[4];
                dp[0] = fma2_(nv, w01.x, dp[0]);
                dp[1] = fma2_(nv, w01.y, dp[1]);
                dp[2] = fma2_(nv, w23.x, dp[2]);
                dp[3] = fma2_(nv, w23.y, dp[3]);
                dp[4] = fma2_(nv, w4,    dp[4]);
            }

            float t[9];
            float sum = 0.f;
            {
                float d[10];
#pragma unroll
                for (int jp = 0; jp < 5; jp++) unpack2_(dp[jp], d[2 * jp], d[2 * jp + 1]);
#pragma unroll
                for (int j = 0; j < 9; j++) {
                    float ev = __expf(a[j] - mx);
                    sum += ev;
                    t[j] = silu_(d[j]) * ev;
                }
            }
            float rs = __fdividef(1.f, sum);

            // grouped projection over output pairs
            u64 tp[9];
#pragma unroll
            for (int j = 0; j < 9; j++) tp[j] = pack1_(t[j] * rs);
#pragma unroll
            for (int j = 0; j < 9; j++) {
                const ulonglong2* op = (const ulonglong2*)&s_ocwT[(cl * 9 + j) * 64 + og * 16];
                ulonglong2 w01 = op[0], w23 = op[1], w45 = op[2], w67 = op[3];
                ap[0] = fma2_(w01.x, tp[j], ap[0]);
                ap[1] = fma2_(w01.y, tp[j], ap[1]);
                ap[2] = fma2_(w23.x, tp[j], ap[2]);
                ap[3] = fma2_(w23.y, tp[j], ap[3]);
                ap[4] = fma2_(w45.x, tp[j], ap[4]);
                ap[5] = fma2_(w45.y, tp[j], ap[5]);
                ap[6] = fma2_(w67.x, tp[j], ap[6]);
                ap[7] = fma2_(w67.y, tp[j], ap[7]);
            }

            // fused 1x1: x_fgca contribution (x center * channel scale)
            u64 xp = pack1_(n[4] * s_scale[c]);
            const ulonglong2* wx = (const ulonglong2*)&s_wsT[(64 + c) * 32];
#pragma unroll
            for (int q = 0; q < 8; q++) {
                ulonglong2 wv = wx[q];
                fp[q * 2 + 0] = fma2_(wv.x, xp, fp[q * 2 + 0]);
                fp[q * 2 + 1] = fma2_(wv.y, xp, fp[q * 2 + 1]);
            }
        }

        // BN + SiLU on rfa outputs, then fused-1x1 x_rfa contribution
#pragma unroll
        for (int q = 0; q < 8; q++) {
            int o = og * 16 + q * 2;
            u64 bsp = *(const u64*)&s_bs[o];
            u64 bbp = *(const u64*)&s_bb[o];
            u64 z = fma2_(ap[q], bsp, bbp);
            float ya, yb;
            unpack2_(z, ya, yb);
            u64 pya = pack1_(silu_(ya));
            u64 pyb = pack1_(silu_(yb));
            const ulonglong2* w0p = (const ulonglong2*)&s_wsT[o * 32];
            const ulonglong2* w1p = (const ulonglong2*)&s_wsT[(o + 1) * 32];
#pragma unroll
            for (int q2 = 0; q2 < 8; q2++) {
                ulonglong2 wa = w0p[q2];
                ulonglong2 wb = w1p[q2];
                fp[q2 * 2 + 0] = fma2_(wa.x, pya, fp[q2 * 2 + 0]);
                fp[q2 * 2 + 1] = fma2_(wa.y, pya, fp[q2 * 2 + 1]);
                fp[q2 * 2 + 0] = fma2_(wb.x, pyb, fp[q2 * 2 + 0]);
                fp[q2 * 2 + 1] = fma2_(wb.y, pyb, fp[q2 * 2 + 1]);
            }
        }
    }

    // epilogue: SiLU + store 32 output channels (fp pairs = adjacent channels)
    float* outp = out + (size_t)(b * 32) * NPIX + pix;
#pragma unroll
    for (int q = 0; q < 16; q++) {
        float ea, eb;
        unpack2_(fp[q], ea, eb);
        outp[(size_t)(2 * q + 0) * NPIX] = silu_(ea);
        outp[(size_t)(2 * q + 1) * NPIX] = silu_(eb);
    }
}

// ==================================================================================
extern "C" void kernel_launch(void* const* d_in, const int* in_sizes, int n_in,
                              void* d_out, int out_size)
{
    const float* x      = (const float*)d_in[0];
    const float* sc_w   = (const float*)d_in[1];
    const float* sc_b   = (const float*)d_in[2];
    const float* ac_w   = (const float*)d_in[3];
    const float* ac_b   = (const float*)d_in[4];
    const float* oc_w   = (const float*)d_in[5];
    const float* oc_b   = (const float*)d_in[6];
    const float* oc_bng = (const float*)d_in[7];
    const float* oc_bnb = (const float*)d_in[8];
    const float* oc_bnm = (const float*)d_in[9];
    const float* oc_bnv = (const float*)d_in[10];
    const float* ex_w   = (const float*)d_in[11];
    const float* ey_w   = (const float*)d_in[12];
    const float* ez_w   = (const float*)d_in[13];
    const float* ff_w   = (const float*)d_in[14];
    const float* ff_b   = (const float*)d_in[15];
    const float* g1_w   = (const float*)d_in[16];
    const float* g1_b   = (const float*)d_in[17];
    const float* g2_w   = (const float*)d_in[18];
    const float* g2_b   = (const float*)d_in[19];
    const float* fu_w   = (const float*)d_in[20];
    const float* fu_b   = (const float*)d_in[21];
    const float* fu_bng = (const float*)d_in[22];
    const float* fu_bnb = (const float*)d_in[23];
    const float* fu_bnm = (const float*)d_in[24];
    const float* fu_bnv = (const float*)d_in[25];

    fft_energy_kernel<<<BB * CC, 256>>>(x);
    gates_kernel<<<BB, 64>>>(ex_w, ey_w, ez_w, ff_w, ff_b, g1_w, g1_b, g2_w, g2_b);
    rfa_fuse_kernel<<<BB * 16, 256>>>(x, sc_w, sc_b, ac_w, ac_b, oc_w, oc_b,
                                      oc_bng, oc_bnb, oc_bnm, oc_bnv,
                                      fu_w, fu_b, fu_bng, fu_bnb, fu_bnm, fu_bnv,
                                      (float*)d_out);
}

// round 10
// speedup vs baseline: 3.0426x; 1.1651x over previous
#include <cuda_runtime.h>
#include <math.h>

#define BB   8
#define CC   64
#define NPIX 4096   // 64*64

typedef unsigned long long u64;

// ---------------- scratch (static device globals; no allocation) ----------------
__device__ float g_mean[BB * CC];
__device__ float g_energy[BB * CC];
__device__ float g_scale[BB * CC];

__device__ __forceinline__ float sigm_(float v) { return __fdividef(1.f, 1.f + __expf(-v)); }
__device__ __forceinline__ float silu_(float v) { return v * __fdividef(1.f, 1.f + __expf(-v)); }

// ---------------- packed fp32x2 helpers (FFMA2 path, sm_100+) ----------------
__device__ __forceinline__ u64 pack2_(float lo, float hi) {
    u64 r; asm("mov.b64 %0, {%1, %2};" : "=l"(r) : "f"(lo), "f"(hi)); return r;
}
__device__ __forceinline__ u64 pack1_(float v) {
    u64 r; asm("mov.b64 %0, {%1, %1};" : "=l"(r) : "f"(v)); return r;
}
__device__ __forceinline__ void unpack2_(u64 p, float& lo, float& hi) {
    asm("mov.b64 {%0, %1}, %2;" : "=f"(lo), "=f"(hi) : "l"(p));
}
__device__ __forceinline__ u64 fma2_(u64 a, u64 b, u64 c) {
    u64 d; asm("fma.rn.f32x2 %0, %1, %2, %3;" : "=l"(d) : "l"(a), "l"(b), "l"(c)); return d;
}

// ---------------- complex helpers (forward convention e^{-2pi i}) ----------------
__device__ __forceinline__ float2 cadd_(float2 a, float2 b) { return make_float2(a.x + b.x, a.y + b.y); }
__device__ __forceinline__ float2 csub_(float2 a, float2 b) { return make_float2(a.x - b.x, a.y - b.y); }
__device__ __forceinline__ float2 cmul_(float2 a, float2 b) {
    return make_float2(a.x * b.x - a.y * b.y, a.x * b.y + a.y * b.x);
}
__device__ __forceinline__ float2 cmni_(float2 a) { return make_float2(a.y, -a.x); }   // a * (-i)

// 8-point forward DFT, natural order in/out. DIT radix-2:
// evens (z0,z2,z4,z6) -> FFT4 E, odds (z1,z3,z5,z7) -> FFT4 O, y = E +- W8^k O.
__device__ __forceinline__ void fft8_(const float2* z, float2* y)
{
    const float Cq = 0.70710678118654752f;
    float2 t0 = cadd_(z[0], z[4]), t1 = csub_(z[0], z[4]);
    float2 t2 = cadd_(z[2], z[6]), t3 = csub_(z[2], z[6]);
    float2 E0 = cadd_(t0, t2), E2 = csub_(t0, t2);
    float2 it3 = cmni_(t3);
    float2 E1 = cadd_(t1, it3), E3 = csub_(t1, it3);
    float2 u0 = cadd_(z[1], z[5]), u1 = csub_(z[1], z[5]);
    float2 u2 = cadd_(z[3], z[7]), u3 = csub_(z[3], z[7]);
    float2 O0 = cadd_(u0, u2), O2 = csub_(u0, u2);
    float2 iu3 = cmni_(u3);
    float2 O1 = cadd_(u1, iu3), O3 = csub_(u1, iu3);
    float2 W1O1 = make_float2(Cq * (O1.x + O1.y), Cq * (O1.y - O1.x));   // * c(1-i)
    float2 W2O2 = cmni_(O2);                                             // * -i
    float2 W3O3 = make_float2(Cq * (O3.y - O3.x), -Cq * (O3.x + O3.y));  // * -c(1+i)
    y[0] = cadd_(E0, O0);   y[4] = csub_(E0, O0);
    y[1] = cadd_(E1, W1O1); y[5] = csub_(E1, W1O1);
    y[2] = cadd_(E2, W2O2); y[6] = csub_(E2, W2O2);
    y[3] = cadd_(E3, W3O3); y[7] = csub_(E3, W3O3);
}

// ==================================================================================
// Kernel 1: per-(b,c) 64x64 FFT2 magnitude mean + spatial mean, radix-8 FFT.
// Rows: two-for-one real-pair trick (32 complex FFT64) + Hermitian unpack (33 cols).
// Cols: 33 complex FFT64, magnitudes summed with Hermitian weights.
// ==================================================================================
__global__ __launch_bounds__(256) void fft_energy_kernel(const float* __restrict__ x)
{
    __shared__ __align__(16) float sA[4352];   // xs -> Zs -> D
    __shared__ __align__(16) float sB[4352];   // C  -> As
    __shared__ float ct[64], st[64];
    __shared__ float red[256];

    const int tid = threadIdx.x;
    const int bc  = blockIdx.x;

    if (tid < 64) {
        float sv, cv;
        sincosf(0.09817477042468103f * (float)tid, &sv, &cv);   // 2*pi/64 * tid
        ct[tid] = cv;
        st[tid] = sv;
    }

    float* xs = sA;
    const float* xp = x + (size_t)bc * NPIX;
    float lsum = 0.f;
    for (int i = tid; i < 4096; i += 256) {
        float v = xp[i];
        xs[i] = v;
        lsum += v;
    }
    red[tid] = lsum;
    __syncthreads();
    for (int s = 128; s > 0; s >>= 1) {
        if (tid < s) red[tid] += red[tid + s];
        __syncthreads();
    }
    if (tid == 0) g_mean[bc] = red[0] * (1.f / 4096.f);

    // ---- P1A: 256 tasks = (pair p, n0). z[n1] = row2p + i*row2p+1 at n0+8n1.
    {
        const int p  = tid >> 3;
        const int n0 = tid & 7;
        float2 z[8], y[8];
        const float* r0 = xs + (2 * p) * 64 + n0;
        const float* r1 = xs + (2 * p + 1) * 64 + n0;
#pragma unroll
        for (int n1 = 0; n1 < 8; n1++) z[n1] = make_float2(r0[8 * n1], r1[8 * n1]);
        fft8_(z, y);
        float2* C = (float2*)sB;
#pragma unroll
        for (int k1 = 0; k1 < 8; k1++) {
            int m = n0 * k1;
            C[(p * 8 + k1) * 8 + n0] = cmul_(y[k1], make_float2(ct[m], -st[m]));
        }
    }
    __syncthreads();
    // ---- P1B: 256 tasks = (p, k1). FFT8 over n0 -> Z[p][k1+8k2].
    {
        const int p  = tid >> 3;
        const int k1 = tid & 7;
        const float2* C = (const float2*)sB;
        float2 z[8], y[8];
#pragma unroll
        for (int n0 = 0; n0 < 8; n0++) z[n0] = C[(p * 8 + k1) * 8 + n0];
        fft8_(z, y);
        float2* Zs = (float2*)sA;   // xs dead
#pragma unroll
        for (int k2 = 0; k2 < 8; k2++) Zs[p * 64 + k1 + 8 * k2] = y[k2];
    }
    __syncthreads();
    // ---- unpack real-pair spectra into As[row][k], k in [0,32]
    {
        const float2* Zs = (const float2*)sA;
        float2* As = (float2*)sB;   // C dead
        for (int t = tid; t < 1056; t += 256) {
            int p = t / 33, k = t - p * 33;
            float2 Zk = Zs[p * 64 + k];
            float2 Zr = Zs[p * 64 + ((64 - k) & 63)];
            // A = (Zk + conj(Zr))/2 ; B = -i(Zk - conj(Zr))/2
            float2 Av = make_float2(0.5f * (Zk.x + Zr.x), 0.5f * (Zk.y - Zr.y));
            float2 Bv = make_float2(0.5f * (Zk.y + Zr.y), 0.5f * (Zr.x - Zk.x));
            As[(2 * p) * 33 + k]     = Av;
            As[(2 * p + 1) * 33 + k] = Bv;
        }
    }
    __syncthreads();
    // ---- P2A: 264 tasks = (col, n0). Column FFT stage 1 + twiddle.
    {
        const float2* As = (const float2*)sB;
        float2* D = (float2*)sA;    // Zs dead
        for (int t = tid; t < 264; t += 256) {
            int col = t >> 3, n0 = t & 7;
            float2 z[8], y[8];
#pragma unroll
            for (int n1 = 0; n1 < 8; n1++) z[n1] = As[(n0 + 8 * n1) * 33 + col];
            fft8_(z, y);
#pragma unroll
            for (int k1 = 0; k1 < 8; k1++) {
                int m = n0 * k1;
                D[(col * 8 + k1) * 8 + n0] = cmul_(y[k1], make_float2(ct[m], -st[m]));
            }
        }
    }
    __syncthreads();
    // ---- P2B: 264 tasks = (col, k1). Stage 2 -> |X| accumulate.
    float esum = 0.f;
    {
        const float2* D = (const float2*)sA;
        for (int t = tid; t < 264; t += 256) {
            int col = t >> 3, k1 = t & 7;
            float2 z[8], y[8];
#pragma unroll
            for (int n0 = 0; n0 < 8; n0++) z[n0] = D[(col * 8 + k1) * 8 + n0];
            fft8_(z, y);
            float s = 0.f;
#pragma unroll
            for (int k2 = 0; k2 < 8; k2++) s += sqrtf(y[k2].x * y[k2].x + y[k2].y * y[k2].y);
            esum += (col == 0 || col == 32) ? s : 2.f * s;
        }
    }
    __syncthreads();
    red[tid] = esum;
    __syncthreads();
    for (int s = 128; s > 0; s >>= 1) {
        if (tid < s) red[tid] += red[tid + s];
        __syncthreads();
    }
    if (tid == 0) g_energy[bc] = red[0] * (1.f / 4096.f);
}

// ==================================================================================
// Kernel 2: FGCA gate pipeline -> per-(b,c) channel scale. One block per batch.
// ==================================================================================
__global__ __launch_bounds__(64) void gates_kernel(
    const float* __restrict__ ex_w, const float* __restrict__ ey_w, const float* __restrict__ ez_w,
    const float* __restrict__ ff_w, const float* __restrict__ ff_b,
    const float* __restrict__ g1_w, const float* __restrict__ g1_b,
    const float* __restrict__ g2_w, const float* __restrict__ g2_b)
{
    const int b = blockIdx.x;
    const int c = threadIdx.x;

    __shared__ float se[64], smn[64], smy[64], smz[64];
    __shared__ float ax[64], ay[64], az[64], af[64], hv[16];

    se[c]  = g_energy[b * 64 + c];
    smn[c] = g_mean[b * 64 + c];
    __syncthreads();

    float e    = se[c];
    int   rank = 0;
#pragma unroll 16
    for (int c2 = 0; c2 < 64; c2++) {
        float e2 = se[c2];
        rank += (e2 > e) || (e2 == e && c2 < c);
    }
    float mask = (rank < 32) ? 1.f : 0.f;
    smy[c] = smn[c] * mask;
    smz[c] = smn[c] * (1.f - mask);
    __syncthreads();

    {
        float w0 = ex_w[0], w1 = ex_w[1], w2 = ex_w[2];
        float v = smn[c] * w1;
        if (c > 0)  v += smn[c - 1] * w0;
        if (c < 63) v += smn[c + 1] * w2;
        ax[c] = sigm_(v);
    }
    {
        float w0 = ey_w[0], w1 = ey_w[1], w2 = ey_w[2];
        float v = smy[c] * w1;
        if (c > 0)  v += smy[c - 1] * w0;
        if (c < 63) v += smy[c + 1] * w2;
        ay[c] = sigm_(v);
    }
    {
        float w0 = ez_w[0], w1 = ez_w[1], w2 = ez_w[2];
        float v = smz[c] * w1;
        if (c > 0)  v += smz[c - 1] * w0;
        if (c < 63) v += smz[c + 1] * w2;
        az[c] = sigm_(v);
    }
    __syncthreads();

    {
        int g = c >> 4;
        const float* src = (g < 2) ? ay : az;
        int base         = (g < 2) ? g * 32 : (g - 2) * 32;
        float s = ff_b[c];
#pragma unroll 8
        for (int j = 0; j < 32; j++) s += ff_w[c * 32 + j] * src[base + j];
        af[c] = s;
    }
    __syncthreads();

    if (c < 16) {
        float hsum = g1_b[c];
#pragma unroll 8
        for (int i = 0; i < 64; i++) hsum += g1_w[c * 128 + i] * af[i];
#pragma unroll 8
        for (int i = 0; i < 64; i++) hsum += g1_w[c * 128 + 64 + i] * ax[i];
        hv[c] = silu_(hsum);
    }
    __syncthreads();

    float gs = g2_b[c];
#pragma unroll
    for (int j = 0; j < 16; j++) gs += g2_w[c * 16 + j] * hv[j];
    float gg = sigm_(gs);

    g_scale[b * 64 + c] = gg * af[c] + (1.f - gg) * ax[c];
}

// ==================================================================================
// Kernel 3: RFA conv + FGCA apply + final 1x1 fuse + BN + SiLU, f32x2-packed,
// software-pipelined channel loads, exp issued ahead of dw conv, no softmax max.
// 256 threads/block, 1 px/thread, grid = B*16.
// ==================================================================================
__device__ __forceinline__ void load_nb_(const float* xc, int h, int w0,
                                         bool has_l, bool has_r, float* n)
{
#pragma unroll
    for (int r = 0; r < 3; r++) {
        int   hh = h + r - 1;
        float v0 = 0.f, v1 = 0.f, v2 = 0.f;
        if (hh >= 0 && hh < 64) {
            const float* rowp = xc + hh * 64;
            v1 = rowp[w0];
            if (has_l) v0 = rowp[w0 - 1];
            if (has_r) v2 = rowp[w0 + 1];
        }
        n[r * 3 + 0] = v0; n[r * 3 + 1] = v1; n[r * 3 + 2] = v2;
    }
}

__global__ __launch_bounds__(256) void rfa_fuse_kernel(
    const float* __restrict__ x,
    const float* __restrict__ sc_w, const float* __restrict__ sc_b,
    const float* __restrict__ ac_w, const float* __restrict__ ac_b,
    const float* __restrict__ oc_w, const float* __restrict__ oc_b,
    const float* __restrict__ bng, const float* __restrict__ bnb,
    const float* __restrict__ bnm, const float* __restrict__ bnv,
    const float* __restrict__ fu_w, const float* __restrict__ fu_b,
    const float* __restrict__ fbng, const float* __restrict__ fbnb,
    const float* __restrict__ fbnm, const float* __restrict__ fbnv,
    float* __restrict__ out)
{
    __shared__ __align__(16) float2 s_scw2[3456];   // [(c*9+tap)*6 + jp] = (w[c,2jp,tap], w[c,2jp+1,tap])
    __shared__ __align__(16) float2 s_scbp[384];    // [c*6+jp] dw bias pairs
    __shared__ __align__(16) float2 s_acwp[384];    // [c*6+jp] att weight pairs
    __shared__ __align__(16) float2 s_acbp[384];    // [c*6+jp] att bias pairs
    __shared__ __align__(16) float  s_ocwT[9216];   // [(cl*9+j)*64 + o]
    __shared__ __align__(16) float  s_wsT[4096];    // [cc 0..127][o 0..31] = fu_w[o][cc]*bnS[o]
    __shared__ __align__(16) float  s_bf[32];
    __shared__ __align__(16) float  s_ob[64], s_bs[64], s_bb[64];
    __shared__ __align__(16) float  s_scale[64], s_s32[32];

    const int tid   = threadIdx.x;
    const int b     = blockIdx.x >> 4;
    const int chunk = blockIdx.x & 15;

    // ---- stage weights
    for (int i = tid; i < 64 * 9 * 5; i += 256) {
        int c2  = i / 45;
        int r   = i - c2 * 45;
        int tap = r / 5;
        int jp  = r - tap * 5;
        int j0  = jp * 2;
        int j1  = (jp == 4) ? 8 : j0 + 1;
        s_scw2[(c2 * 9 + tap) * 6 + jp] =
            make_float2(sc_w[(c2 * 9 + j0) * 9 + tap], sc_w[(c2 * 9 + j1) * 9 + tap]);
    }
    for (int i = tid; i < 64 * 5; i += 256) {
        int c2 = i / 5, jp = i - c2 * 5;
        int j0 = jp * 2;
        int j1 = (jp == 4) ? 8 : j0 + 1;
        s_scbp[c2 * 6 + jp] = make_float2(sc_b[c2 * 9 + j0], sc_b[c2 * 9 + j1]);
        s_acwp[c2 * 6 + jp] = make_float2(ac_w[c2 * 9 + j0], ac_w[c2 * 9 + j1]);
        s_acbp[c2 * 6 + jp] = make_float2(ac_b[c2 * 9 + j0], ac_b[c2 * 9 + j1]);
    }
    for (int i = tid; i < 9216; i += 256) {
        int o = i / 144, r = i - o * 144;
        int cl = r / 9,  j = r - cl * 9;
        s_ocwT[(cl * 9 + j) * 64 + o] = oc_w[i];
    }
    if (tid < 64) {
        float s = bng[tid] * rsqrtf(bnv[tid] + 1e-5f);
        s_bs[tid]    = s;
        s_bb[tid]    = bnb[tid] - bnm[tid] * s;
        s_ob[tid]    = oc_b[tid];
        s_scale[tid] = g_scale[b * 64 + tid];
    }
    if (tid < 32) {
        float s = fbng[tid] * rsqrtf(fbnv[tid] + 1e-5f);
        s_s32[tid] = s;
        s_bf[tid]  = fu_b[tid] * s + fbnb[tid] - fbnm[tid] * s;
    }
    __syncthreads();
    for (int i = tid; i < 4096; i += 256) {
        int o = i & 31, cc = i >> 5;
        s_wsT[i] = fu_w[o * 128 + cc] * s_s32[o];
    }
    __syncthreads();

    const int pix = chunk * 256 + tid;
    const int h   = pix >> 6;
    const int w0  = pix & 63;
    const float* xb = x + (size_t)b * CC * NPIX;
    const bool has_l = (w0 > 0);
    const bool has_r = (w0 < 63);

    // fused 1x1 accumulators: pairs of adjacent output channels
    u64 fp[16];
#pragma unroll
    for (int q = 0; q < 16; q++) fp[q] = *(const u64*)&s_bf[q * 2];

    // software pipeline: preload channel 0 neighborhood
    float ncur[9], nnext[9];
    load_nb_(xb, h, w0, has_l, has_r, ncur);

    for (int og = 0; og < 4; og++) {
        u64 ap[8];
#pragma unroll
        for (int q = 0; q < 8; q++) ap[q] = *(const u64*)&s_ob[og * 16 + q * 2];

#pragma unroll 2
        for (int cl = 0; cl < 16; cl++) {
            const int c = og * 16 + cl;
            if (c < 63) load_nb_(xb + (size_t)(c + 1) * NPIX, h, w0, has_l, has_r, nnext);

            float p = ((((ncur[0] + ncur[1]) + (ncur[2] + ncur[3])) +
                        ((ncur[5] + ncur[6]) + (ncur[7] + ncur[8]))) + ncur[4]) * (1.f / 9.f);

            // softmax numerators (no max subtraction: logits bounded small here);
            // issue all exps + sum rcp BEFORE the dw-conv fma block to hide MUFU latency
            float e[9];
            {
                u64 pp = pack1_(p);
                const u64* wq = (const u64*)&s_acwp[c * 6];
                const u64* bq = (const u64*)&s_acbp[c * 6];
                float a0, a1, dum;
                u64 lg;
                lg = fma2_(pp, wq[0], bq[0]); unpack2_(lg, a0, a1); e[0] = __expf(a0); e[1] = __expf(a1);
                lg = fma2_(pp, wq[1], bq[1]); unpack2_(lg, a0, a1); e[2] = __expf(a0); e[3] = __expf(a1);
                lg = fma2_(pp, wq[2], bq[2]); unpack2_(lg, a0, a1); e[4] = __expf(a0); e[5] = __expf(a1);
                lg = fma2_(pp, wq[3], bq[3]); unpack2_(lg, a0, a1); e[6] = __expf(a0); e[7] = __expf(a1);
                lg = fma2_(pp, wq[4], bq[4]); unpack2_(lg, a0, dum); e[8] = __expf(a0);
            }
            float sum = ((((e[0] + e[1]) + (e[2] + e[3])) +
                          ((e[4] + e[5]) + (e[6] + e[7]))) + e[8]);
            float rs = __fdividef(1.f, sum);

            // dw conv over taps, RF positions packed in pairs
            u64 dp[5];
            {
                const u64* bq = (const u64*)&s_scbp[c * 6];
#pragma unroll
                for (int jp = 0; jp < 5; jp++) dp[jp] = bq[jp];
            }
#pragma unroll
            for (int tap = 0; tap < 9; tap++) {
                u64 nv = pack1_(ncur[tap]);
                const u64* wp = (const u64*)&s_scw2[(c * 9 + tap) * 6];
                ulonglong2 w01 = ((const ulonglong2*)wp)[0];
                ulonglong2 w23 = ((const ulonglong2*)wp)[1];
                u64        w4  = wp[4];
                dp[0] = fma2_(nv, w01.x, dp[0]);
                dp[1] = fma2_(nv, w01.y, dp[1]);
                dp[2] = fma2_(nv, w23.x, dp[2]);
                dp[3] = fma2_(nv, w23.y, dp[3]);
                dp[4] = fma2_(nv, w4,    dp[4]);
            }

            float t[9];
            {
                float d[10];
#pragma unroll
                for (int jp = 0; jp < 5; jp++) unpack2_(dp[jp], d[2 * jp], d[2 * jp + 1]);
#pragma unroll
                for (int j = 0; j < 9; j++) t[j] = silu_(d[j]) * e[j];
            }

            // grouped projection over output pairs
            u64 tp[9];
#pragma unroll
            for (int j = 0; j < 9; j++) tp[j] = pack1_(t[j] * rs);
#pragma unroll
            for (int j = 0; j < 9; j++) {
                const ulonglong2* op = (const ulonglong2*)&s_ocwT[(cl * 9 + j) * 64 + og * 16];
                ulonglong2 w01 = op[0], w23 = op[1], w45 = op[2], w67 = op[3];
                ap[0] = fma2_(w01.x, tp[j], ap[0]);
                ap[1] = fma2_(w01.y, tp[j], ap[1]);
                ap[2] = fma2_(w23.x, tp[j], ap[2]);
                ap[3] = fma2_(w23.y, tp[j], ap[3]);
                ap[4] = fma2_(w45.x, tp[j], ap[4]);
                ap[5] = fma2_(w45.y, tp[j], ap[5]);
                ap[6] = fma2_(w67.x, tp[j], ap[6]);
                ap[7] = fma2_(w67.y, tp[j], ap[7]);
            }

            // fused 1x1: x_fgca contribution (x center * channel scale)
            u64 xp = pack1_(ncur[4] * s_scale[c]);
            const ulonglong2* wx = (const ulonglong2*)&s_wsT[(64 + c) * 32];
#pragma unroll
            for (int q = 0; q < 8; q++) {
                ulonglong2 wv = wx[q];
                fp[q * 2 + 0] = fma2_(wv.x, xp, fp[q * 2 + 0]);
                fp[q * 2 + 1] = fma2_(wv.y, xp, fp[q * 2 + 1]);
            }

            // rotate pipeline registers
#pragma unroll
            for (int q = 0; q < 9; q++) ncur[q] = nnext[q];
        }

        // BN + SiLU on rfa outputs, then fused-1x1 x_rfa contribution
#pragma unroll
        for (int q = 0; q < 8; q++) {
            int o = og * 16 + q * 2;
            u64 bsp = *(const u64*)&s_bs[o];
            u64 bbp = *(const u64*)&s_bb[o];
            u64 z = fma2_(ap[q], bsp, bbp);
            float ya, yb;
            unpack2_(z, ya, yb);
            u64 pya = pack1_(silu_(ya));
            u64 pyb = pack1_(silu_(yb));
            const ulonglong2* w0p = (const ulonglong2*)&s_wsT[o * 32];
            const ulonglong2* w1p = (const ulonglong2*)&s_wsT[(o + 1) * 32];
#pragma unroll
            for (int q2 = 0; q2 < 8; q2++) {
                ulonglong2 wa = w0p[q2];
                ulonglong2 wb = w1p[q2];
                fp[q2 * 2 + 0] = fma2_(wa.x, pya, fp[q2 * 2 + 0]);
                fp[q2 * 2 + 1] = fma2_(wa.y, pya, fp[q2 * 2 + 1]);
                fp[q2 * 2 + 0] = fma2_(wb.x, pyb, fp[q2 * 2 + 0]);
                fp[q2 * 2 + 1] = fma2_(wb.y, pyb, fp[q2 * 2 + 1]);
            }
        }
    }

    // epilogue: SiLU + store 32 output channels (fp pairs = adjacent channels)
    float* outp = out + (size_t)(b * 32) * NPIX + pix;
#pragma unroll
    for (int q = 0; q < 16; q++) {
        float ea, eb;
        unpack2_(fp[q], ea, eb);
        outp[(size_t)(2 * q + 0) * NPIX] = silu_(ea);
        outp[(size_t)(2 * q + 1) * NPIX] = silu_(eb);
    }
}

// ==================================================================================
extern "C" void kernel_launch(void* const* d_in, const int* in_sizes, int n_in,
                              void* d_out, int out_size)
{
    const float* x      = (const float*)d_in[0];
    const float* sc_w   = (const float*)d_in[1];
    const float* sc_b   = (const float*)d_in[2];
    const float* ac_w   = (const float*)d_in[3];
    const float* ac_b   = (const float*)d_in[4];
    const float* oc_w   = (const float*)d_in[5];
    const float* oc_b   = (const float*)d_in[6];
    const float* oc_bng = (const float*)d_in[7];
    const float* oc_bnb = (const float*)d_in[8];
    const float* oc_bnm = (const float*)d_in[9];
    const float* oc_bnv = (const float*)d_in[10];
    const float* ex_w   = (const float*)d_in[11];
    const float* ey_w   = (const float*)d_in[12];
    const float* ez_w   = (const float*)d_in[13];
    const float* ff_w   = (const float*)d_in[14];
    const float* ff_b   = (const float*)d_in[15];
    const float* g1_w   = (const float*)d_in[16];
    const float* g1_b   = (const float*)d_in[17];
    const float* g2_w   = (const float*)d_in[18];
    const float* g2_b   = (const float*)d_in[19];
    const float* fu_w   = (const float*)d_in[20];
    const float* fu_b   = (const float*)d_in[21];
    const float* fu_bng = (const float*)d_in[22];
    const float* fu_bnb = (const float*)d_in[23];
    const float* fu_bnm = (const float*)d_in[24];
    const float* fu_bnv = (const float*)d_in[25];

    fft_energy_kernel<<<BB * CC, 256>>>(x);
    gates_kernel<<<BB, 64>>>(ex_w, ey_w, ez_w, ff_w, ff_b, g1_w, g1_b, g2_w, g2_b);
    rfa_fuse_kernel<<<BB * 16, 256>>>(x, sc_w, sc_b, ac_w, ac_b, oc_w, oc_b,
                                      oc_bng, oc_bnb, oc_bnm, oc_bnv,
                                      fu_w, fu_b, fu_bng, fu_bnb, fu_bnm, fu_bnv,
                                      (float*)d_out);
}